// round 8
// baseline (speedup 1.0000x reference)
#include <cuda_runtime.h>
#include <cuda_fp16.h>

#define NN 100000
#define EE 1600000
#define GG 128
#define SCAN_B 1024
#define SCAN_NBLK ((NN + SCAN_B - 1) / SCAN_B)   // 98
#define GR 128   // gemm rows per block
#define SIS 132  // sInT stride (multiple of 4 -> 16B-aligned float4 rows)

// ---------------- scratch (static device globals; no allocation) ----------------
// degcnt: count<<48 | (wdeg-1.0)*2^32  -> required init is ZERO (self-loop folded in)
__device__ __align__(16) unsigned long long g_degcnt[NN];
__device__ __align__(16) float g_dinv[NN];
__device__ __align__(16) int   g_offs[NN + 1];
__device__ __align__(16) int   g_cursor[NN];
__device__ __align__(16) int   g_bsum[SCAN_NBLK + 1];
__device__ __align__(16) int2  g_payload[EE];            // {src, (w*dinv[src])-as-bits} sorted by dest
__device__ __align__(16) __half g_bufA[(size_t)NN * 64]; // h (gemm output, fp16)
__device__ __align__(16) __half g_bufC[(size_t)NN * 64]; // conv output layers 1-2 (fp16)
__device__ __align__(16) float g_bufB[(size_t)NN * 64];  // conv output layer 3 (fp32, pooled)
__device__ __align__(16) float g_pooled[GG * 64];        // zero-init; reset by pool kernel
__device__ int g_poolctr;                                // zero-init; reset by pool kernel
__device__ __align__(16) float g_bnsc[3][64];
__device__ __align__(16) float g_bnsh[3][64];

struct BNParams { const float* p[12]; };  // (gamma,beta,mean,var) x 3 layers

__device__ __forceinline__ unsigned long long ffma2(unsigned long long a,
                                                    unsigned long long b,
                                                    unsigned long long c) {
    unsigned long long d;
    asm("fma.rn.f32x2 %0, %1, %2, %3;" : "=l"(d) : "l"(a), "l"(b), "l"(c));
    return d;
}
__device__ __forceinline__ unsigned long long rep2(float a) {
    unsigned long long d;
    unsigned ai = __float_as_uint(a);
    asm("mov.b64 %0, {%1, %1};" : "=l"(d) : "r"(ai));
    return d;
}

// ---------------- degcount: packed 64-bit atomic + BN const computation ----------------
__global__ void k_degcount(const int* __restrict__ col, const float* __restrict__ w,
                           BNParams bp) {
    int e = blockIdx.x * blockDim.x + threadIdx.x;
    if (e < 3 * 64) {                 // BN scale/shift (once per replay, fused here)
        int l = e >> 6, f = e & 63;
        const float* ga = bp.p[l * 4 + 0];
        const float* be = bp.p[l * 4 + 1];
        const float* mn = bp.p[l * 4 + 2];
        const float* va = bp.p[l * 4 + 3];
        float sc = ga[f] * rsqrtf(va[f] + 1e-5f);
        g_bnsc[l][f] = sc;
        g_bnsh[l][f] = be[f] - mn[f] * sc;
    }
    if (e >= EE) return;
    unsigned long long pack = (1ULL << 48) + (unsigned long long)(w[e] * 4294967296.0f);
    atomicAdd(&g_degcnt[col[e]], pack);
}

// ---------------- scan phase 1: warp-shfl block scan ----------------
__global__ void k_scan1() {
    __shared__ int ws[32];
    int t = threadIdx.x;
    int lane = t & 31, w = t >> 5;
    int i = blockIdx.x * SCAN_B + t;
    int val = (i < NN) ? (int)(g_degcnt[i] >> 48) : 0;
    int x = val;
#pragma unroll
    for (int off = 1; off < 32; off <<= 1) {
        int y = __shfl_up_sync(0xFFFFFFFFu, x, off);
        if (lane >= off) x += y;
    }
    if (lane == 31) ws[w] = x;
    __syncthreads();
    if (w == 0) {
        int s = ws[lane];
#pragma unroll
        for (int off = 1; off < 32; off <<= 1) {
            int y = __shfl_up_sync(0xFFFFFFFFu, s, off);
            if (lane >= off) s += y;
        }
        ws[lane] = s;          // inclusive warp-sum scan
    }
    __syncthreads();
    int base = (w == 0) ? 0 : ws[w - 1];
    if (i < NN) g_offs[i] = base + x - val;       // exclusive within block
    if (t == SCAN_B - 1) g_bsum[blockIdx.x] = ws[31];
}

// ---------------- fix: redundant per-block scan of 98 block sums + finalize ----------------
__global__ void k_fix() {
    __shared__ int sb[SCAN_NBLK];
    int t = threadIdx.x;   // 256
    if (t < 32) {          // warp 0 scans the 98 block sums into sb (exclusive)
        int carry = 0;
        for (int base = 0; base < SCAN_NBLK; base += 32) {
            int i = base + t;
            int v = (i < SCAN_NBLK) ? g_bsum[i] : 0;
            int x = v;
#pragma unroll
            for (int off = 1; off < 32; off <<= 1) {
                int y = __shfl_up_sync(0xFFFFFFFFu, x, off);
                if (t >= off) x += y;
            }
            if (i < SCAN_NBLK) sb[i] = carry + x - v;
            carry += __shfl_sync(0xFFFFFFFFu, x, 31);
        }
    }
    __syncthreads();
    int i = blockIdx.x * blockDim.x + t;
    if (i < NN) {
        int o = g_offs[i] + sb[i >> 10];
        g_offs[i] = o;
        g_cursor[i] = o;
        // deg = 1.0 (self loop) + fixed-point accumulated weight
        float deg = 1.0f + (float)(g_degcnt[i] & 0xFFFFFFFFFFFFULL) * (1.0f / 4294967296.0f);
        g_dinv[i] = rsqrtf(deg);
    }
    if (i == 0) g_offs[NN] = EE;
}

// scatter edges into dest-sorted order; payload = {src, w*dinv[src]}; resets degcnt
__global__ void k_scatter(const int* __restrict__ row, const int* __restrict__ col,
                          const float* __restrict__ w) {
    int e = blockIdx.x * blockDim.x + threadIdx.x;
    if (e < NN) g_degcnt[e] = 0ULL;    // reset for next replay (fix already consumed it)
    if (e >= EE) return;
    int r = row[e];
    int c = col[e];
    float nv = g_dinv[r] * w[e];
    int pos = atomicAdd(&g_cursor[c], 1);
    g_payload[pos] = make_int2(r, __float_as_int(nv));
}

// ---------------- register-blocked GEMM with packed f32x2 FMA ----------------
template <int ACT, int IN16>
__device__ __forceinline__ void gemm_body(const void* __restrict__ in_,
                                          const float* __restrict__ W, int l) {
    __shared__ __align__(16) float sW[64 * 64];          // [k][c]
    __shared__ __align__(16) float sInT[64 * SIS];       // [k][r], padded (SIS % 4 == 0)
    int t = threadIdx.x;  // 128

    const float4* W4 = (const float4*)W;
    float4* sW4 = (float4*)sW;
#pragma unroll
    for (int i = 0; i < 8; i++) sW4[t + 128 * i] = W4[t + 128 * i];

    int r0 = blockIdx.x * GR;
    if (IN16) {
        const __half* in = (const __half*)in_;
#pragma unroll
        for (int i = 0; i < 8; i++) {
            int idx = t + 128 * i;       // 0..1023 uint4s (8 halves each)
            int rr = idx >> 3;
            int cc = (idx & 7) * 8;
            int gr = r0 + rr;
            uint4 v = make_uint4(0, 0, 0, 0);
            if (gr < NN) v = *(const uint4*)(in + (size_t)gr * 64 + cc);
            float f[8];
            float2 p;
            p = __half22float2(*(__half2*)&v.x); f[0] = p.x; f[1] = p.y;
            p = __half22float2(*(__half2*)&v.y); f[2] = p.x; f[3] = p.y;
            p = __half22float2(*(__half2*)&v.z); f[4] = p.x; f[5] = p.y;
            p = __half22float2(*(__half2*)&v.w); f[6] = p.x; f[7] = p.y;
#pragma unroll
            for (int j = 0; j < 8; j++) {
                float fv = f[j];
                if (ACT == 1) fv = fmaxf(fv, 0.f) * g_bnsc[l][cc + j] + g_bnsh[l][cc + j];
                sInT[(cc + j) * SIS + rr] = fv;
            }
        }
    } else {
        const float* in = (const float*)in_;
#pragma unroll
        for (int i = 0; i < 16; i++) {
            int idx = t + 128 * i;        // 0..2047 float4s in 128x64 tile
            int rr = idx >> 4;
            int cc = (idx & 15) * 4;
            int gr = r0 + rr;
            float4 v = make_float4(0.f, 0.f, 0.f, 0.f);
            if (gr < NN) v = *(const float4*)(in + (size_t)gr * 64 + cc);
            if (ACT == 1) {
                v.x = fmaxf(v.x, 0.f) * g_bnsc[l][cc + 0] + g_bnsh[l][cc + 0];
                v.y = fmaxf(v.y, 0.f) * g_bnsc[l][cc + 1] + g_bnsh[l][cc + 1];
                v.z = fmaxf(v.z, 0.f) * g_bnsc[l][cc + 2] + g_bnsh[l][cc + 2];
                v.w = fmaxf(v.w, 0.f) * g_bnsc[l][cc + 3] + g_bnsh[l][cc + 3];
            }
            sInT[(cc + 0) * SIS + rr] = v.x;
            sInT[(cc + 1) * SIS + rr] = v.y;
            sInT[(cc + 2) * SIS + rr] = v.z;
            sInT[(cc + 3) * SIS + rr] = v.w;
        }
    }
    __syncthreads();

    int tr = t >> 3;                  // 0..15 row group
    int tc = t & 7;                   // 0..7  col group
    int rbase = tr * 8;
    int cbase = tc * 8;

    unsigned long long acc[8][4];
#pragma unroll
    for (int r = 0; r < 8; r++)
#pragma unroll
        for (int j = 0; j < 4; j++) acc[r][j] = 0ull;

#pragma unroll
    for (int k = 0; k < 64; k++) {
        float4 a0 = *(const float4*)&sInT[k * SIS + rbase];
        float4 a1 = *(const float4*)&sInT[k * SIS + rbase + 4];
        ulonglong2 wlo = *(const ulonglong2*)&sW[k * 64 + cbase];
        ulonglong2 whi = *(const ulonglong2*)&sW[k * 64 + cbase + 4];
        unsigned long long ap[8];
        ap[0] = rep2(a0.x); ap[1] = rep2(a0.y); ap[2] = rep2(a0.z); ap[3] = rep2(a0.w);
        ap[4] = rep2(a1.x); ap[5] = rep2(a1.y); ap[6] = rep2(a1.z); ap[7] = rep2(a1.w);
#pragma unroll
        for (int r = 0; r < 8; r++) {
            acc[r][0] = ffma2(ap[r], wlo.x, acc[r][0]);
            acc[r][1] = ffma2(ap[r], wlo.y, acc[r][1]);
            acc[r][2] = ffma2(ap[r], whi.x, acc[r][2]);
            acc[r][3] = ffma2(ap[r], whi.y, acc[r][3]);
        }
    }

#pragma unroll
    for (int r = 0; r < 8; r++) {
        int gr = r0 + rbase + r;
        if (gr >= NN) break;
        float2 c0 = *(float2*)&acc[r][0];
        float2 c1 = *(float2*)&acc[r][1];
        float2 c2 = *(float2*)&acc[r][2];
        float2 c3 = *(float2*)&acc[r][3];
        __half2 h0 = __floats2half2_rn(c0.x, c0.y);
        __half2 h1 = __floats2half2_rn(c1.x, c1.y);
        __half2 h2 = __floats2half2_rn(c2.x, c2.y);
        __half2 h3 = __floats2half2_rn(c3.x, c3.y);
        *(uint4*)&g_bufA[(size_t)gr * 64 + cbase] =
            make_uint4(*(unsigned*)&h0, *(unsigned*)&h1,
                       *(unsigned*)&h2, *(unsigned*)&h3);
    }
}

__global__ void __launch_bounds__(128) k_gemm1(const float* __restrict__ x,
                                               const float* __restrict__ W) {
    gemm_body<0, 0>(x, W, 0);
}
__global__ void __launch_bounds__(128) k_gemm23(const float* __restrict__ W, int l) {
    gemm_body<1, 1>(g_bufC, W, l);
}

// ---------------- CSR aggregation (warp per destination, 4x8 lane groups) ----------------
template <int OUT16>
__global__ void __launch_bounds__(256) k_agg(const float* __restrict__ bias) {
    int warp = threadIdx.x >> 5;
    int lane = threadIdx.x & 31;
    int c = blockIdx.x * 8 + warp;          // NN % 8 == 0
    int grp = lane >> 3;                    // 0..3: stride-4 edge groups
    int q = lane & 7;                       // owns halves [8q, 8q+7] = one uint4
    int e = g_offs[c] + grp;
    int end = g_offs[c + 1];

    const uint4* __restrict__ A4 = (const uint4*)g_bufA;   // 8 uint4 per 64-feat row

    float acc[8] = {0.f, 0.f, 0.f, 0.f, 0.f, 0.f, 0.f, 0.f};
    for (; e < end; e += 4) {
        int2 p = __ldg(&g_payload[e]);
        uint4 r = __ldg(&A4[(size_t)p.x * 8 + q]);
        float n = __int_as_float(p.y);
        float2 f;
        f = __half22float2(*(__half2*)&r.x); acc[0] += f.x * n; acc[1] += f.y * n;
        f = __half22float2(*(__half2*)&r.y); acc[2] += f.x * n; acc[3] += f.y * n;
        f = __half22float2(*(__half2*)&r.z); acc[4] += f.x * n; acc[5] += f.y * n;
        f = __half22float2(*(__half2*)&r.w); acc[6] += f.x * n; acc[7] += f.y * n;
    }
#pragma unroll
    for (int j = 0; j < 8; j++) {
        acc[j] += __shfl_xor_sync(0xFFFFFFFFu, acc[j], 8);
        acc[j] += __shfl_xor_sync(0xFFFFFFFFu, acc[j], 16);
    }

    if (grp == 0) {
        float dv = g_dinv[c];
        float snv = dv * dv;
        uint4 sr = __ldg(&A4[(size_t)c * 8 + q]);
        float s[8];
        float2 f;
        f = __half22float2(*(__half2*)&sr.x); s[0] = f.x; s[1] = f.y;
        f = __half22float2(*(__half2*)&sr.y); s[2] = f.x; s[3] = f.y;
        f = __half22float2(*(__half2*)&sr.z); s[4] = f.x; s[5] = f.y;
        f = __half22float2(*(__half2*)&sr.w); s[6] = f.x; s[7] = f.y;
        float4 b0 = *(const float4*)(bias + q * 8);
        float4 b1 = *(const float4*)(bias + q * 8 + 4);
        float o[8];
        o[0] = acc[0] * dv + s[0] * snv + b0.x;
        o[1] = acc[1] * dv + s[1] * snv + b0.y;
        o[2] = acc[2] * dv + s[2] * snv + b0.z;
        o[3] = acc[3] * dv + s[3] * snv + b0.w;
        o[4] = acc[4] * dv + s[4] * snv + b1.x;
        o[5] = acc[5] * dv + s[5] * snv + b1.y;
        o[6] = acc[6] * dv + s[6] * snv + b1.z;
        o[7] = acc[7] * dv + s[7] * snv + b1.w;
        if (OUT16) {
            __half2 h0 = __floats2half2_rn(o[0], o[1]);
            __half2 h1 = __floats2half2_rn(o[2], o[3]);
            __half2 h2 = __floats2half2_rn(o[4], o[5]);
            __half2 h3 = __floats2half2_rn(o[6], o[7]);
            *(uint4*)&g_bufC[(size_t)c * 64 + q * 8] =
                make_uint4(*(unsigned*)&h0, *(unsigned*)&h1,
                           *(unsigned*)&h2, *(unsigned*)&h3);
        } else {
            *(float4*)&g_bufB[(size_t)c * 64 + q * 8]     = make_float4(o[0], o[1], o[2], o[3]);
            *(float4*)&g_bufB[(size_t)c * 64 + q * 8 + 4] = make_float4(o[4], o[5], o[6], o[7]);
        }
    }
}

// ---------------- BN3 + global_add_pool + fused FC (last-block pattern) ----------------
#define POOL_CHUNK 128
__global__ void k_poolfc(const int* __restrict__ batch,
                         const float* __restrict__ Wfc, const float* __restrict__ bfc,
                         float* __restrict__ out) {
    int f = threadIdx.x;  // 64 threads: one per feature
    int start = blockIdx.x * POOL_CHUNK;
    int end = start + POOL_CHUNK;
    if (end > NN) end = NN;
    if (start < NN) {
        float sc = g_bnsc[2][f], sh = g_bnsh[2][f];
        int cur = batch[start];
        float acc = 0.f;
        for (int n = start; n < end; n++) {
            int b = batch[n];
            if (b != cur) {
                atomicAdd(&g_pooled[cur * 64 + f], acc);
                acc = 0.f;
                cur = b;
            }
            acc += g_bufB[(size_t)n * 64 + f] * sc + sh;
        }
        atomicAdd(&g_pooled[cur * 64 + f], acc);
    }

    // last block computes FC and resets pooled/counter for the next replay
    __threadfence();
    __shared__ int lastflag;
    if (threadIdx.x == 0)
        lastflag = (atomicAdd(&g_poolctr, 1) == gridDim.x - 1) ? 1 : 0;
    __syncthreads();
    if (lastflag) {
        for (int g = threadIdx.x; g < GG; g += 64) {
            float acc = 0.f;
#pragma unroll
            for (int k = 0; k < 64; k++)
                acc += fmaxf(__ldcg(&g_pooled[g * 64 + k]), 0.f) * Wfc[k];
            out[g] = acc + bfc[0];
        }
        __syncthreads();
        for (int i = threadIdx.x; i < GG * 64; i += 64) g_pooled[i] = 0.f;
        if (threadIdx.x == 0) g_poolctr = 0;
    }
}

// ---------------- launch ----------------
extern "C" void kernel_launch(void* const* d_in, const int* in_sizes, int n_in,
                              void* d_out, int out_size) {
    const float* x     = (const float*)d_in[0];
    const int*   ei    = (const int*)d_in[1];
    const int*   row   = ei;
    const int*   col   = ei + EE;
    const float* ew    = (const float*)d_in[2];
    const int*   batch = (const int*)d_in[3];
    const float* W1 = (const float*)d_in[4];
    const float* b1 = (const float*)d_in[5];
    const float* W2 = (const float*)d_in[6];
    const float* b2 = (const float*)d_in[7];
    const float* W3 = (const float*)d_in[8];
    const float* b3 = (const float*)d_in[9];
    const float* Wfc = (const float*)d_in[10];
    const float* bfc = (const float*)d_in[11];

    BNParams bp;
    for (int i = 0; i < 12; i++) bp.p[i] = (const float*)d_in[12 + i];

    int nb_e = (EE + 255) / 256;          // 6250
    int nb_fix = (NN + 255) / 256;        // 391
    int nb_gemm = (NN + GR - 1) / GR;     // 782
    int nb_agg = NN / 8;                  // 12500
    int nb_pool = (NN + POOL_CHUNK - 1) / POOL_CHUNK; // 782

    // CSR build (4 kernels)
    k_degcount<<<nb_e, 256>>>(col, ew, bp);
    k_scan1<<<SCAN_NBLK, SCAN_B>>>();
    k_fix<<<nb_fix, 256>>>();
    k_scatter<<<nb_e, 256>>>(row, col, ew);

    // layer 1
    k_gemm1<<<nb_gemm, 128>>>(x, W1);
    k_agg<1><<<nb_agg, 256>>>(b1);
    // layer 2 (relu + bn1 fused into gemm input)
    k_gemm23<<<nb_gemm, 128>>>(W2, 0);
    k_agg<1><<<nb_agg, 256>>>(b2);
    // layer 3 (relu + bn2 fused into gemm input)
    k_gemm23<<<nb_gemm, 128>>>(W3, 1);
    k_agg<0><<<nb_agg, 256>>>(b3);

    // bn3 + pool + fc (single kernel)
    k_poolfc<<<nb_pool, 64>>>(batch, Wfc, bfc, (float*)d_out);
}

// round 9
// speedup vs baseline: 1.1006x; 1.1006x over previous
#include <cuda_runtime.h>
#include <cuda_fp16.h>

#define NN 100000
#define EE 1600000
#define GG 128
#define GR 128   // gemm rows per block
#define SIS 132  // sInT stride (multiple of 4 -> 16B-aligned float4 rows)
#define SLOT 64  // payload slots per destination (Poisson(16) max << 64)

// ---------------- scratch (static device globals; no allocation) ----------------
__device__ __align__(16) float g_dinv[NN];                 // Sigma(w) accumulator -> rsqrt(1+.) in place
__device__ __align__(16) int   g_cursor[NN];
__device__ __align__(16) int2  g_pay[(size_t)NN * SLOT];   // {src, w-as-bits} binned by dest
__device__ __align__(16) __half g_bufA[(size_t)NN * 64];   // h*dinv (gemm output, fp16)
__device__ __align__(16) float g_bufB[(size_t)NN * 64];    // conv output (fp32)
__device__ __align__(16) float g_pooled[GG * 64];
__device__ __align__(16) float g_bnsc[3][64];
__device__ __align__(16) float g_bnsh[3][64];

struct BNParams { const float* p[12]; };  // (gamma,beta,mean,var) x 3 layers

__device__ __forceinline__ unsigned long long ffma2(unsigned long long a,
                                                    unsigned long long b,
                                                    unsigned long long c) {
    unsigned long long d;
    asm("fma.rn.f32x2 %0, %1, %2, %3;" : "=l"(d) : "l"(a), "l"(b), "l"(c));
    return d;
}
__device__ __forceinline__ unsigned long long rep2(float a) {
    unsigned long long d;
    unsigned ai = __float_as_uint(a);
    asm("mov.b64 %0, {%1, %1};" : "=l"(d) : "r"(ai));
    return d;
}

// ---------------- prep: zero accumulators, BN consts ----------------
__global__ void k_prep(BNParams bp) {
    int i = blockIdx.x * blockDim.x + threadIdx.x;
    if (i < NN) { g_dinv[i] = 0.0f; g_cursor[i] = 0; }
    if (i < GG * 64) g_pooled[i] = 0.0f;
    if (i < 3 * 64) {
        int l = i >> 6, f = i & 63;
        const float* ga = bp.p[l * 4 + 0];
        const float* be = bp.p[l * 4 + 1];
        const float* mn = bp.p[l * 4 + 2];
        const float* va = bp.p[l * 4 + 3];
        float sc = ga[f] * rsqrtf(va[f] + 1e-5f);
        g_bnsc[l][f] = sc;
        g_bnsh[l][f] = be[f] - mn[f] * sc;
    }
}

// weighted in-degree (f32 reduction, no return needed)
__global__ void k_degw(const int* __restrict__ col, const float* __restrict__ w) {
    int e = blockIdx.x * blockDim.x + threadIdx.x;
    if (e < EE) atomicAdd(&g_dinv[col[e]], w[e]);
}

// finalize dinv in place + bin edges by destination; payload = {src, w}
__global__ void k_scatter(const int* __restrict__ row, const int* __restrict__ col,
                          const float* __restrict__ w) {
    int e = blockIdx.x * blockDim.x + threadIdx.x;
    if (e < NN) g_dinv[e] = rsqrtf(1.0f + g_dinv[e]);   // no other thread reads dinv here
    if (e >= EE) return;
    int r = row[e];
    int c = col[e];
    int pos = atomicAdd(&g_cursor[c], 1);
    if (pos > SLOT - 1) pos = SLOT - 1;                 // unreachable; memory safety only
    g_pay[(size_t)c * SLOT + pos] = make_int2(r, __float_as_int(w[e]));
}

// ---------------- register-blocked GEMM with packed f32x2 FMA ----------------
// 128 threads, tile 128 rows x 64 cols; micro 8x8 per thread.
// epilogue: bufA = (row result) * dinv[row]  (fp16)
template <int ACT>
__device__ __forceinline__ void gemm_body(const float* __restrict__ in,
                                          const float* __restrict__ W, int l) {
    __shared__ __align__(16) float sW[64 * 64];          // [k][c]
    __shared__ __align__(16) float sInT[64 * SIS];       // [k][r]
    int t = threadIdx.x;  // 128

    const float4* W4 = (const float4*)W;
    float4* sW4 = (float4*)sW;
#pragma unroll
    for (int i = 0; i < 8; i++) sW4[t + 128 * i] = W4[t + 128 * i];

    int r0 = blockIdx.x * GR;
#pragma unroll
    for (int i = 0; i < 16; i++) {
        int idx = t + 128 * i;        // 0..2047 float4s in 128x64 tile
        int rr = idx >> 4;
        int cc = (idx & 15) * 4;
        int gr = r0 + rr;
        float4 v = make_float4(0.f, 0.f, 0.f, 0.f);
        if (gr < NN) v = *(const float4*)(in + (size_t)gr * 64 + cc);
        if (ACT == 1) {
            v.x = fmaxf(v.x, 0.f) * g_bnsc[l][cc + 0] + g_bnsh[l][cc + 0];
            v.y = fmaxf(v.y, 0.f) * g_bnsc[l][cc + 1] + g_bnsh[l][cc + 1];
            v.z = fmaxf(v.z, 0.f) * g_bnsc[l][cc + 2] + g_bnsh[l][cc + 2];
            v.w = fmaxf(v.w, 0.f) * g_bnsc[l][cc + 3] + g_bnsh[l][cc + 3];
        }
        sInT[(cc + 0) * SIS + rr] = v.x;
        sInT[(cc + 1) * SIS + rr] = v.y;
        sInT[(cc + 2) * SIS + rr] = v.z;
        sInT[(cc + 3) * SIS + rr] = v.w;
    }
    __syncthreads();

    int tr = t >> 3;                  // 0..15 row group
    int tc = t & 7;                   // 0..7  col group
    int rbase = tr * 8;
    int cbase = tc * 8;

    unsigned long long acc[8][4];
#pragma unroll
    for (int r = 0; r < 8; r++)
#pragma unroll
        for (int j = 0; j < 4; j++) acc[r][j] = 0ull;

#pragma unroll
    for (int k = 0; k < 64; k++) {
        float4 a0 = *(const float4*)&sInT[k * SIS + rbase];
        float4 a1 = *(const float4*)&sInT[k * SIS + rbase + 4];
        ulonglong2 wlo = *(const ulonglong2*)&sW[k * 64 + cbase];
        ulonglong2 whi = *(const ulonglong2*)&sW[k * 64 + cbase + 4];
        unsigned long long ap[8];
        ap[0] = rep2(a0.x); ap[1] = rep2(a0.y); ap[2] = rep2(a0.z); ap[3] = rep2(a0.w);
        ap[4] = rep2(a1.x); ap[5] = rep2(a1.y); ap[6] = rep2(a1.z); ap[7] = rep2(a1.w);
#pragma unroll
        for (int r = 0; r < 8; r++) {
            acc[r][0] = ffma2(ap[r], wlo.x, acc[r][0]);
            acc[r][1] = ffma2(ap[r], wlo.y, acc[r][1]);
            acc[r][2] = ffma2(ap[r], whi.x, acc[r][2]);
            acc[r][3] = ffma2(ap[r], whi.y, acc[r][3]);
        }
    }

#pragma unroll
    for (int r = 0; r < 8; r++) {
        int gr = r0 + rbase + r;
        if (gr >= NN) break;
        float dv = g_dinv[gr];
        float2 c0 = *(float2*)&acc[r][0];
        float2 c1 = *(float2*)&acc[r][1];
        float2 c2 = *(float2*)&acc[r][2];
        float2 c3 = *(float2*)&acc[r][3];
        __half2 h0 = __floats2half2_rn(c0.x * dv, c0.y * dv);
        __half2 h1 = __floats2half2_rn(c1.x * dv, c1.y * dv);
        __half2 h2 = __floats2half2_rn(c2.x * dv, c2.y * dv);
        __half2 h3 = __floats2half2_rn(c3.x * dv, c3.y * dv);
        *(uint4*)&g_bufA[(size_t)gr * 64 + cbase] =
            make_uint4(*(unsigned*)&h0, *(unsigned*)&h1,
                       *(unsigned*)&h2, *(unsigned*)&h3);
    }
}

__global__ void __launch_bounds__(128) k_gemm1(const float* __restrict__ x,
                                               const float* __restrict__ W) {
    gemm_body<0>(x, W, 0);
}
__global__ void __launch_bounds__(128) k_gemm23(const float* __restrict__ W, int l) {
    gemm_body<1>(g_bufB, W, l);
}

// ---------------- binned aggregation (warp per destination) ----------------
// bufB[c] = dinv[c] * ( sum_e w_e * bufA'[src_e] + bufA'[c] ) + bias
// two 16-lane halves take alternating edges; lane q owns uint2 (4 features).
__global__ void __launch_bounds__(256) k_agg(const float* __restrict__ bias) {
    int warp = threadIdx.x >> 5;
    int lane = threadIdx.x & 31;
    int c = blockIdx.x * 8 + warp;          // NN % 8 == 0
    int half = lane >> 4;
    int q = lane & 15;
    int cnt = g_cursor[c];
    const int2* __restrict__ pay = g_pay + (size_t)c * SLOT;

    const uint2* __restrict__ A2 = (const uint2*)g_bufA;   // 16 uint2 per 64-feat row

    float4 acc = make_float4(0.f, 0.f, 0.f, 0.f);
    for (int e = half; e < cnt; e += 2) {
        int2 p = __ldg(&pay[e]);
        uint2 r = __ldg(&A2[(size_t)p.x * 16 + q]);
        float n = __int_as_float(p.y);
        float2 f0 = __half22float2(*(__half2*)&r.x);
        float2 f1 = __half22float2(*(__half2*)&r.y);
        acc.x += f0.x * n; acc.y += f0.y * n;
        acc.z += f1.x * n; acc.w += f1.y * n;
    }
    acc.x += __shfl_xor_sync(0xFFFFFFFFu, acc.x, 16);
    acc.y += __shfl_xor_sync(0xFFFFFFFFu, acc.y, 16);
    acc.z += __shfl_xor_sync(0xFFFFFFFFu, acc.z, 16);
    acc.w += __shfl_xor_sync(0xFFFFFFFFu, acc.w, 16);

    if (half == 0) {
        float dv = g_dinv[c];
        uint2 sr = __ldg(&A2[(size_t)c * 16 + q]);         // bufA'[c] = h[c]*dinv[c]
        float2 s0 = __half22float2(*(__half2*)&sr.x);
        float2 s1 = __half22float2(*(__half2*)&sr.y);
        float4 b = *(const float4*)(bias + q * 4);
        float4 o;
        o.x = (acc.x + s0.x) * dv + b.x;
        o.y = (acc.y + s0.y) * dv + b.y;
        o.z = (acc.z + s1.x) * dv + b.z;
        o.w = (acc.w + s1.y) * dv + b.w;
        *(float4*)&g_bufB[(size_t)c * 64 + q * 4] = o;
    }
}

// ---------------- BN3 + global_add_pool (batch is sorted: run-accumulate) ----------------
#define POOL_CHUNK 128
__global__ void k_pool(const int* __restrict__ batch) {
    int f = threadIdx.x;  // 64 threads: one per feature
    int start = blockIdx.x * POOL_CHUNK;
    int end = start + POOL_CHUNK;
    if (end > NN) end = NN;
    if (start >= NN) return;
    float sc = g_bnsc[2][f], sh = g_bnsh[2][f];
    int cur = batch[start];
    float acc = 0.f;
    for (int n = start; n < end; n++) {
        int b = batch[n];
        if (b != cur) {
            atomicAdd(&g_pooled[cur * 64 + f], acc);
            acc = 0.f;
            cur = b;
        }
        acc += g_bufB[(size_t)n * 64 + f] * sc + sh;
    }
    atomicAdd(&g_pooled[cur * 64 + f], acc);
}

// ---------------- FC: out[g] = relu(pooled[g]) . Wfc + bfc ----------------
__global__ void k_fc(const float* __restrict__ Wfc, const float* __restrict__ bfc,
                     float* __restrict__ out) {
    int g = threadIdx.x;  // 128
    float acc = 0.f;
#pragma unroll
    for (int k = 0; k < 64; k++)
        acc += fmaxf(g_pooled[g * 64 + k], 0.f) * Wfc[k];
    out[g] = acc + bfc[0];
}

// ---------------- launch ----------------
extern "C" void kernel_launch(void* const* d_in, const int* in_sizes, int n_in,
                              void* d_out, int out_size) {
    const float* x     = (const float*)d_in[0];
    const int*   ei    = (const int*)d_in[1];
    const int*   row   = ei;
    const int*   col   = ei + EE;
    const float* ew    = (const float*)d_in[2];
    const int*   batch = (const int*)d_in[3];
    const float* W1 = (const float*)d_in[4];
    const float* b1 = (const float*)d_in[5];
    const float* W2 = (const float*)d_in[6];
    const float* b2 = (const float*)d_in[7];
    const float* W3 = (const float*)d_in[8];
    const float* b3 = (const float*)d_in[9];
    const float* Wfc = (const float*)d_in[10];
    const float* bfc = (const float*)d_in[11];

    BNParams bp;
    for (int i = 0; i < 12; i++) bp.p[i] = (const float*)d_in[12 + i];

    int nb_n = (NN + 255) / 256;          // 391
    int nb_e = (EE + 255) / 256;          // 6250
    int nb_gemm = (NN + GR - 1) / GR;     // 782
    int nb_agg = NN / 8;                  // 12500
    int nb_pool = (NN + POOL_CHUNK - 1) / POOL_CHUNK; // 782

    // CSR-free build: weighted degree + 64-slot binning (3 kernels)
    k_prep<<<nb_n, 256>>>(bp);
    k_degw<<<nb_e, 256>>>(col, ew);
    k_scatter<<<nb_e, 256>>>(row, col, ew);

    // layer 1
    k_gemm1<<<nb_gemm, 128>>>(x, W1);
    k_agg<<<nb_agg, 256>>>(b1);
    // layer 2 (relu + bn1 fused into gemm input)
    k_gemm23<<<nb_gemm, 128>>>(W2, 0);
    k_agg<<<nb_agg, 256>>>(b2);
    // layer 3 (relu + bn2 fused into gemm input)
    k_gemm23<<<nb_gemm, 128>>>(W3, 1);
    k_agg<<<nb_agg, 256>>>(b3);

    // bn3 (no relu) + pool, then fc
    k_pool<<<nb_pool, 64>>>(batch);
    k_fc<<<1, 128>>>(Wfc, bfc, (float*)d_out);
}

// round 11
// speedup vs baseline: 1.3282x; 1.2068x over previous
#include <cuda_runtime.h>
#include <cuda_fp16.h>
#include <stdint.h>

#define NN 100000
#define EE 1600000
#define GG 128
#define SLOT 64  // payload slots per destination (Poisson(16) max << 64)

// ---------------- scratch (static device globals; no allocation) ----------------
__device__ __align__(16) float g_dinv[NN];                 // Sigma(w) accumulator -> rsqrt(1+.) in place
__device__ __align__(16) int   g_cursor[NN];
__device__ __align__(16) int2  g_pay[(size_t)NN * SLOT];   // {src, w-as-bits} binned by dest
__device__ __align__(16) __half g_bufA[(size_t)NN * 64];   // h*dinv (gemm output, fp16)
__device__ __align__(16) __half g_bufC[(size_t)NN * 64];   // conv output layers 1-2 (fp16)
__device__ __align__(16) float g_bufB[(size_t)NN * 64];    // conv output layer 3 (fp32)
__device__ __align__(16) float g_pooled[GG * 64];
__device__ __align__(16) float g_bnsc[3][64];
__device__ __align__(16) float g_bnsh[3][64];

struct BNParams { const float* p[12]; };  // (gamma,beta,mean,var) x 3 layers

// ---------------- mma helpers ----------------
__device__ __forceinline__ unsigned s2u(const void* p) {
    unsigned a;
    asm("{ .reg .u64 t; cvta.to.shared.u64 t, %1; cvt.u32.u64 %0, t; }" : "=r"(a) : "l"(p));
    return a;
}
__device__ __forceinline__ void ldsm_x4(unsigned& r0, unsigned& r1, unsigned& r2, unsigned& r3,
                                        unsigned addr) {
    asm volatile("ldmatrix.sync.aligned.m8n8.x4.shared.b16 {%0,%1,%2,%3}, [%4];"
                 : "=r"(r0), "=r"(r1), "=r"(r2), "=r"(r3) : "r"(addr));
}
__device__ __forceinline__ void ldsm_x4t(unsigned& r0, unsigned& r1, unsigned& r2, unsigned& r3,
                                         unsigned addr) {
    asm volatile("ldmatrix.sync.aligned.m8n8.x4.trans.shared.b16 {%0,%1,%2,%3}, [%4];"
                 : "=r"(r0), "=r"(r1), "=r"(r2), "=r"(r3) : "r"(addr));
}
__device__ __forceinline__ void mma16816(float* c, unsigned a0, unsigned a1, unsigned a2,
                                         unsigned a3, unsigned b0, unsigned b1) {
    asm volatile(
        "mma.sync.aligned.m16n8k16.row.col.f32.f16.f16.f32 "
        "{%0,%1,%2,%3}, {%4,%5,%6,%7}, {%8,%9}, {%0,%1,%2,%3};"
        : "+f"(c[0]), "+f"(c[1]), "+f"(c[2]), "+f"(c[3])
        : "r"(a0), "r"(a1), "r"(a2), "r"(a3), "r"(b0), "r"(b1));
}

// ---------------- prep: zero accumulators, BN consts ----------------
__global__ void k_prep(BNParams bp) {
    int i = blockIdx.x * blockDim.x + threadIdx.x;
    if (i < NN) { g_dinv[i] = 0.0f; g_cursor[i] = 0; }
    if (i < GG * 64) g_pooled[i] = 0.0f;
    if (i < 3 * 64) {
        int l = i >> 6, f = i & 63;
        const float* ga = bp.p[l * 4 + 0];
        const float* be = bp.p[l * 4 + 1];
        const float* mn = bp.p[l * 4 + 2];
        const float* va = bp.p[l * 4 + 3];
        float sc = ga[f] * rsqrtf(va[f] + 1e-5f);
        g_bnsc[l][f] = sc;
        g_bnsh[l][f] = be[f] - mn[f] * sc;
    }
}

// weighted in-degree
__global__ void k_degw(const int* __restrict__ col, const float* __restrict__ w) {
    int e = blockIdx.x * blockDim.x + threadIdx.x;
    if (e < EE) atomicAdd(&g_dinv[col[e]], w[e]);
}

// finalize dinv in place + bin edges by destination; payload = {src, w}
__global__ void k_scatter(const int* __restrict__ row, const int* __restrict__ col,
                          const float* __restrict__ w) {
    int e = blockIdx.x * blockDim.x + threadIdx.x;
    if (e < NN) g_dinv[e] = rsqrtf(1.0f + g_dinv[e]);
    if (e >= EE) return;
    int r = row[e];
    int c = col[e];
    int pos = atomicAdd(&g_cursor[c], 1);
    if (pos > SLOT - 1) pos = SLOT - 1;                 // unreachable; memory safety only
    g_pay[(size_t)c * SLOT + pos] = make_int2(r, __float_as_int(w[e]));
}

// ---------------- tensor-core GEMM core: bufA = (act(in) @ W) * dinv[row]  (fp16 out) ----------
// 128 threads / 4 warps; block tile 64 rows x 64 cols; warp tile 16 rows x 64 cols.
// in32 != nullptr: fp32 input, no act (layer 1). Else: fp16 input from g_bufC with ReLU+BN(l).
__device__ __forceinline__ void gemm_core(const float* in32, const float* W, int l) {
    __shared__ __align__(16) __half sA[64 * 72];   // row r at r*72 (144B stride, 16B aligned)
    __shared__ __align__(16) __half sW[64 * 72];   // k row at k*72
    int t = threadIdx.x;
    int r0 = blockIdx.x * 64;

    // stage W (fp32 -> fp16)
    const float4* W4 = (const float4*)W;
#pragma unroll
    for (int j = 0; j < 8; j++) {
        int idx = t + 128 * j;            // 1024 float4 = 64x64 fp32
        float4 v = W4[idx];
        int k = idx >> 4, c4 = idx & 15;
        __half2 h0 = __floats2half2_rn(v.x, v.y);
        __half2 h1 = __floats2half2_rn(v.z, v.w);
        *(uint2*)&sW[k * 72 + c4 * 4] = make_uint2(*(unsigned*)&h0, *(unsigned*)&h1);
    }

    // stage input rows (apply act in fp32, store fp16)
    if (in32 != 0) {
#pragma unroll
        for (int j = 0; j < 8; j++) {
            int idx = t + 128 * j;
            int rr = idx >> 4, c4 = idx & 15;
            int gr = r0 + rr;
            float4 v = make_float4(0.f, 0.f, 0.f, 0.f);
            if (gr < NN) v = *(const float4*)(in32 + (size_t)gr * 64 + c4 * 4);
            __half2 h0 = __floats2half2_rn(v.x, v.y);
            __half2 h1 = __floats2half2_rn(v.z, v.w);
            *(uint2*)&sA[rr * 72 + c4 * 4] = make_uint2(*(unsigned*)&h0, *(unsigned*)&h1);
        }
    } else {
        const __half* in = g_bufC;
#pragma unroll
        for (int j = 0; j < 4; j++) {
            int idx = t + 128 * j;
            int rr = idx >> 3, c8 = (idx & 7) * 8;
            int gr = r0 + rr;
            uint4 v = make_uint4(0, 0, 0, 0);
            if (gr < NN) v = *(const uint4*)(in + (size_t)gr * 64 + c8);
            float f[8];
            float2 p;
            p = __half22float2(*(__half2*)&v.x); f[0] = p.x; f[1] = p.y;
            p = __half22float2(*(__half2*)&v.y); f[2] = p.x; f[3] = p.y;
            p = __half22float2(*(__half2*)&v.z); f[4] = p.x; f[5] = p.y;
            p = __half22float2(*(__half2*)&v.w); f[6] = p.x; f[7] = p.y;
#pragma unroll
            for (int i = 0; i < 8; i++)
                f[i] = fmaxf(f[i], 0.f) * g_bnsc[l][c8 + i] + g_bnsh[l][c8 + i];
            __half2 h0 = __floats2half2_rn(f[0], f[1]);
            __half2 h1 = __floats2half2_rn(f[2], f[3]);
            __half2 h2 = __floats2half2_rn(f[4], f[5]);
            __half2 h3 = __floats2half2_rn(f[6], f[7]);
            *(uint4*)&sA[rr * 72 + c8] = make_uint4(*(unsigned*)&h0, *(unsigned*)&h1,
                                                    *(unsigned*)&h2, *(unsigned*)&h3);
        }
    }
    __syncthreads();

    int warp = t >> 5, lane = t & 31;
    int mrow = warp * 16;
    unsigned aBase = s2u(sA), wBase = s2u(sW);
    int sub = lane >> 3, lr = lane & 7;

    float acc[8][4];
#pragma unroll
    for (int j = 0; j < 8; j++)
#pragma unroll
        for (int i = 0; i < 4; i++) acc[j][i] = 0.f;

#pragma unroll
    for (int kk = 0; kk < 4; kk++) {
        // A frag tiles: M0 rows0-7/kLo, M1 rows8-15/kLo, M2 rows0-7/kHi, M3 rows8-15/kHi
        int arow = mrow + (sub & 1) * 8 + lr;
        int acol = kk * 16 + (sub >> 1) * 8;
        unsigned a0, a1, a2, a3;
        ldsm_x4(a0, a1, a2, a3, aBase + (unsigned)(arow * 72 + acol) * 2);
#pragma unroll
        for (int jj = 0; jj < 4; jj++) {
            // B frag tiles (trans): M0 kLo/n(2jj), M1 kHi/n(2jj), M2 kLo/n(2jj+1), M3 kHi/n(2jj+1)
            int brow = kk * 16 + (sub & 1) * 8 + lr;
            int bcol = (jj * 2 + (sub >> 1)) * 8;
            unsigned b0, b1, b2, b3;
            ldsm_x4t(b0, b1, b2, b3, wBase + (unsigned)(brow * 72 + bcol) * 2);
            mma16816(acc[jj * 2],     a0, a1, a2, a3, b0, b1);
            mma16816(acc[jj * 2 + 1], a0, a1, a2, a3, b2, b3);
        }
    }

    // epilogue: c0/c1 -> row g1, c2/c3 -> row g2 = g1+8; cols j*8 + 2*(lane&3)
    int g1 = r0 + mrow + (lane >> 2);
    int g2 = g1 + 8;
    int cq = (lane & 3) * 2;
    float dv1 = (g1 < NN) ? g_dinv[g1] : 0.f;
    float dv2 = (g2 < NN) ? g_dinv[g2] : 0.f;
#pragma unroll
    for (int j = 0; j < 8; j++) {
        if (g1 < NN) {
            __half2 h = __floats2half2_rn(acc[j][0] * dv1, acc[j][1] * dv1);
            *(__half2*)&g_bufA[(size_t)g1 * 64 + j * 8 + cq] = h;
        }
        if (g2 < NN) {
            __half2 h = __floats2half2_rn(acc[j][2] * dv2, acc[j][3] * dv2);
            *(__half2*)&g_bufA[(size_t)g2 * 64 + j * 8 + cq] = h;
        }
    }
}

__global__ void __launch_bounds__(128) k_gemm1(const float* __restrict__ x,
                                               const float* __restrict__ W) {
    gemm_core(x, W, 0);
}
__global__ void __launch_bounds__(128) k_gemm23(const float* __restrict__ W, int l) {
    gemm_core(0, W, l);
}

// ---------------- binned aggregation (warp per destination) ----------------
// out[c] = dinv[c] * ( sum_e w_e * bufA'[src_e] + bufA'[c] ) + bias
// out16=1 -> fp16 g_bufC (layers 1-2); out16=0 -> fp32 g_bufB (layer 3)
__global__ void __launch_bounds__(256) k_agg(const float* __restrict__ bias, int out16) {
    int warp = threadIdx.x >> 5;
    int lane = threadIdx.x & 31;
    int c = blockIdx.x * 8 + warp;          // NN % 8 == 0
    int half = lane >> 4;
    int q = lane & 15;
    int cnt = g_cursor[c];
    const int2* __restrict__ pay = g_pay + (size_t)c * SLOT;

    const uint2* __restrict__ A2 = (const uint2*)g_bufA;   // 16 uint2 per 64-feat row

    float4 acc = make_float4(0.f, 0.f, 0.f, 0.f);
    for (int e = half; e < cnt; e += 2) {
        int2 p = __ldg(&pay[e]);
        uint2 r = __ldg(&A2[(size_t)p.x * 16 + q]);
        float n = __int_as_float(p.y);
        float2 f0 = __half22float2(*(__half2*)&r.x);
        float2 f1 = __half22float2(*(__half2*)&r.y);
        acc.x += f0.x * n; acc.y += f0.y * n;
        acc.z += f1.x * n; acc.w += f1.y * n;
    }
    acc.x += __shfl_xor_sync(0xFFFFFFFFu, acc.x, 16);
    acc.y += __shfl_xor_sync(0xFFFFFFFFu, acc.y, 16);
    acc.z += __shfl_xor_sync(0xFFFFFFFFu, acc.z, 16);
    acc.w += __shfl_xor_sync(0xFFFFFFFFu, acc.w, 16);

    if (half == 0) {
        float dv = g_dinv[c];
        uint2 sr = __ldg(&A2[(size_t)c * 16 + q]);         // bufA'[c] = h[c]*dinv[c]
        float2 s0 = __half22float2(*(__half2*)&sr.x);
        float2 s1 = __half22float2(*(__half2*)&sr.y);
        float4 b = *(const float4*)(bias + q * 4);
        float4 o;
        o.x = (acc.x + s0.x) * dv + b.x;
        o.y = (acc.y + s0.y) * dv + b.y;
        o.z = (acc.z + s1.x) * dv + b.z;
        o.w = (acc.w + s1.y) * dv + b.w;
        if (out16) {
            __half2 h0 = __floats2half2_rn(o.x, o.y);
            __half2 h1 = __floats2half2_rn(o.z, o.w);
            *(uint2*)&g_bufC[(size_t)c * 64 + q * 4] =
                make_uint2(*(unsigned*)&h0, *(unsigned*)&h1);
        } else {
            *(float4*)&g_bufB[(size_t)c * 64 + q * 4] = o;
        }
    }
}

// ---------------- BN3 + global_add_pool (batch is sorted: run-accumulate) ----------------
#define POOL_CHUNK 128
__global__ void k_pool(const int* __restrict__ batch) {
    int f = threadIdx.x;  // 64 threads: one per feature
    int start = blockIdx.x * POOL_CHUNK;
    int end = start + POOL_CHUNK;
    if (end > NN) end = NN;
    if (start >= NN) return;
    float sc = g_bnsc[2][f], sh = g_bnsh[2][f];
    int cur = batch[start];
    float acc = 0.f;
    for (int n = start; n < end; n++) {
        int b = batch[n];
        if (b != cur) {
            atomicAdd(&g_pooled[cur * 64 + f], acc);
            acc = 0.f;
            cur = b;
        }
        acc += g_bufB[(size_t)n * 64 + f] * sc + sh;
    }
    atomicAdd(&g_pooled[cur * 64 + f], acc);
}

// ---------------- FC: out[g] = relu(pooled[g]) . Wfc + bfc ----------------
__global__ void k_fc(const float* __restrict__ Wfc, const float* __restrict__ bfc,
                     float* __restrict__ out) {
    int g = threadIdx.x;  // 128
    float acc = 0.f;
#pragma unroll
    for (int k = 0; k < 64; k++)
        acc += fmaxf(g_pooled[g * 64 + k], 0.f) * Wfc[k];
    out[g] = acc + bfc[0];
}

// ---------------- launch ----------------
extern "C" void kernel_launch(void* const* d_in, const int* in_sizes, int n_in,
                              void* d_out, int out_size) {
    const float* x     = (const float*)d_in[0];
    const int*   ei    = (const int*)d_in[1];
    const int*   row   = ei;
    const int*   col   = ei + EE;
    const float* ew    = (const float*)d_in[2];
    const int*   batch = (const int*)d_in[3];
    const float* W1 = (const float*)d_in[4];
    const float* b1 = (const float*)d_in[5];
    const float* W2 = (const float*)d_in[6];
    const float* b2 = (const float*)d_in[7];
    const float* W3 = (const float*)d_in[8];
    const float* b3 = (const float*)d_in[9];
    const float* Wfc = (const float*)d_in[10];
    const float* bfc = (const float*)d_in[11];

    BNParams bp;
    for (int i = 0; i < 12; i++) bp.p[i] = (const float*)d_in[12 + i];

    int nb_n = (NN + 255) / 256;            // 391
    int nb_e = (EE + 255) / 256;            // 6250
    int nb_gemm = (NN + 63) / 64;           // 1563
    int nb_agg = NN / 8;                    // 12500
    int nb_pool = (NN + POOL_CHUNK - 1) / POOL_CHUNK; // 782

    // CSR-free build
    k_prep<<<nb_n, 256>>>(bp);
    k_degw<<<nb_e, 256>>>(col, ew);
    k_scatter<<<nb_e, 256>>>(row, col, ew);

    // layer 1 (fp32 input, no act)
    k_gemm1<<<nb_gemm, 128>>>(x, W1);
    k_agg<<<nb_agg, 256>>>(b1, 1);
    // layer 2 (relu + bn1 on fp16 input)
    k_gemm23<<<nb_gemm, 128>>>(W2, 0);
    k_agg<<<nb_agg, 256>>>(b2, 1);
    // layer 3 (relu + bn2 on fp16 input)
    k_gemm23<<<nb_gemm, 128>>>(W3, 1);
    k_agg<<<nb_agg, 256>>>(b3, 0);

    // bn3 (no relu) + pool, then fc
    k_pool<<<nb_pool, 64>>>(batch);
    k_fc<<<1, 128>>>(Wfc, bfc, (float*)d_out);
}

// round 12
// speedup vs baseline: 1.5016x; 1.1306x over previous
#include <cuda_runtime.h>
#include <cuda_fp16.h>
#include <stdint.h>

#define NN 100000
#define EE 1600000
#define GG 128
#define SLOT 64  // payload slots per destination (Poisson(16) max << 64)

// ---------------- scratch (static device globals; no allocation) ----------------
__device__ __align__(16) float g_dinv[NN];                 // Sigma(w) accumulator -> rsqrt(1+.) in place
__device__ __align__(16) int   g_cursor[NN];
__device__ __align__(16) int2  g_pay[(size_t)NN * SLOT];   // {src, w-as-bits} binned by dest
__device__ __align__(16) __half g_bufA[(size_t)NN * 64];   // h*dinv (gemm output, fp16)
__device__ __align__(16) __half g_bufC[(size_t)NN * 64];   // conv output layers 1-2 (fp16)
__device__ __align__(16) float g_pooled[GG * 64];
__device__ __align__(16) float g_bnsc[3][64];
__device__ __align__(16) float g_bnsh[3][64];

struct BNParams { const float* p[12]; };  // (gamma,beta,mean,var) x 3 layers

// ---------------- mma helpers ----------------
__device__ __forceinline__ unsigned s2u(const void* p) {
    unsigned a;
    asm("{ .reg .u64 t; cvta.to.shared.u64 t, %1; cvt.u32.u64 %0, t; }" : "=r"(a) : "l"(p));
    return a;
}
__device__ __forceinline__ void ldsm_x4(unsigned& r0, unsigned& r1, unsigned& r2, unsigned& r3,
                                        unsigned addr) {
    asm volatile("ldmatrix.sync.aligned.m8n8.x4.shared.b16 {%0,%1,%2,%3}, [%4];"
                 : "=r"(r0), "=r"(r1), "=r"(r2), "=r"(r3) : "r"(addr));
}
__device__ __forceinline__ void ldsm_x4t(unsigned& r0, unsigned& r1, unsigned& r2, unsigned& r3,
                                         unsigned addr) {
    asm volatile("ldmatrix.sync.aligned.m8n8.x4.trans.shared.b16 {%0,%1,%2,%3}, [%4];"
                 : "=r"(r0), "=r"(r1), "=r"(r2), "=r"(r3) : "r"(addr));
}
__device__ __forceinline__ void mma16816(float* c, unsigned a0, unsigned a1, unsigned a2,
                                         unsigned a3, unsigned b0, unsigned b1) {
    asm volatile(
        "mma.sync.aligned.m16n8k16.row.col.f32.f16.f16.f32 "
        "{%0,%1,%2,%3}, {%4,%5,%6,%7}, {%8,%9}, {%0,%1,%2,%3};"
        : "+f"(c[0]), "+f"(c[1]), "+f"(c[2]), "+f"(c[3])
        : "r"(a0), "r"(a1), "r"(a2), "r"(a3), "r"(b0), "r"(b1));
}

// ---------------- prep: zero accumulators, BN consts ----------------
__global__ void k_prep(BNParams bp) {
    int i = blockIdx.x * blockDim.x + threadIdx.x;
    if (i < NN) { g_dinv[i] = 0.0f; g_cursor[i] = 0; }
    if (i < GG * 64) g_pooled[i] = 0.0f;
    if (i < 3 * 64) {
        int l = i >> 6, f = i & 63;
        const float* ga = bp.p[l * 4 + 0];
        const float* be = bp.p[l * 4 + 1];
        const float* mn = bp.p[l * 4 + 2];
        const float* va = bp.p[l * 4 + 3];
        float sc = ga[f] * rsqrtf(va[f] + 1e-5f);
        g_bnsc[l][f] = sc;
        g_bnsh[l][f] = be[f] - mn[f] * sc;
    }
}

// weighted in-degree
__global__ void k_degw(const int* __restrict__ col, const float* __restrict__ w) {
    int e = blockIdx.x * blockDim.x + threadIdx.x;
    if (e < EE) atomicAdd(&g_dinv[col[e]], w[e]);
}

// finalize dinv in place + bin edges by destination; payload = {src, w}
__global__ void k_scatter(const int* __restrict__ row, const int* __restrict__ col,
                          const float* __restrict__ w) {
    int e = blockIdx.x * blockDim.x + threadIdx.x;
    if (e < NN) g_dinv[e] = rsqrtf(1.0f + g_dinv[e]);
    if (e >= EE) return;
    int r = row[e];
    int c = col[e];
    int pos = atomicAdd(&g_cursor[c], 1);
    if (pos > SLOT - 1) pos = SLOT - 1;                 // unreachable; memory safety only
    g_pay[(size_t)c * SLOT + pos] = make_int2(r, __float_as_int(w[e]));
}

// ---------------- tensor-core GEMM: bufA = (act(in) @ W) * dinv[row]  (fp16 out) ----------
// 128 threads / 4 warps; block covers 4 tiles of 64 rows (256 rows); W staged once.
// in32 != nullptr: fp32 input, no act (layer 1). Else: fp16 input from g_bufC with ReLU+BN(l).
__device__ __forceinline__ void gemm_core(const float* in32, const float* W, int l) {
    __shared__ __align__(16) __half sA[64 * 72];   // row r at r*72 (144B stride, 16B aligned)
    __shared__ __align__(16) __half sW[64 * 72];   // k row at k*72
    int t = threadIdx.x;

    // stage W (fp32 -> fp16) once
    const float4* W4 = (const float4*)W;
#pragma unroll
    for (int j = 0; j < 8; j++) {
        int idx = t + 128 * j;            // 1024 float4 = 64x64 fp32
        float4 v = W4[idx];
        int k = idx >> 4, c4 = idx & 15;
        __half2 h0 = __floats2half2_rn(v.x, v.y);
        __half2 h1 = __floats2half2_rn(v.z, v.w);
        *(uint2*)&sW[k * 72 + c4 * 4] = make_uint2(*(unsigned*)&h0, *(unsigned*)&h1);
    }

    int warp = t >> 5, lane = t & 31;
    int mrow = warp * 16;
    unsigned aBase = s2u(sA), wBase = s2u(sW);
    int sub = lane >> 3, lr = lane & 7;

    for (int tile = 0; tile < 4; tile++) {
        int r0 = (blockIdx.x * 4 + tile) * 64;
        __syncthreads();   // W staged (1st iter) / all warps done reading sA (later iters)

        // stage input rows (apply act in fp32, store fp16)
        if (in32 != 0) {
#pragma unroll
            for (int j = 0; j < 8; j++) {
                int idx = t + 128 * j;
                int rr = idx >> 4, c4 = idx & 15;
                int gr = r0 + rr;
                float4 v = make_float4(0.f, 0.f, 0.f, 0.f);
                if (gr < NN) v = *(const float4*)(in32 + (size_t)gr * 64 + c4 * 4);
                __half2 h0 = __floats2half2_rn(v.x, v.y);
                __half2 h1 = __floats2half2_rn(v.z, v.w);
                *(uint2*)&sA[rr * 72 + c4 * 4] = make_uint2(*(unsigned*)&h0, *(unsigned*)&h1);
            }
        } else {
            const __half* in = g_bufC;
#pragma unroll
            for (int j = 0; j < 4; j++) {
                int idx = t + 128 * j;
                int rr = idx >> 3, c8 = (idx & 7) * 8;
                int gr = r0 + rr;
                uint4 v = make_uint4(0, 0, 0, 0);
                if (gr < NN) v = *(const uint4*)(in + (size_t)gr * 64 + c8);
                float f[8];
                float2 p;
                p = __half22float2(*(__half2*)&v.x); f[0] = p.x; f[1] = p.y;
                p = __half22float2(*(__half2*)&v.y); f[2] = p.x; f[3] = p.y;
                p = __half22float2(*(__half2*)&v.z); f[4] = p.x; f[5] = p.y;
                p = __half22float2(*(__half2*)&v.w); f[6] = p.x; f[7] = p.y;
#pragma unroll
                for (int i = 0; i < 8; i++)
                    f[i] = fmaxf(f[i], 0.f) * g_bnsc[l][c8 + i] + g_bnsh[l][c8 + i];
                __half2 h0 = __floats2half2_rn(f[0], f[1]);
                __half2 h1 = __floats2half2_rn(f[2], f[3]);
                __half2 h2 = __floats2half2_rn(f[4], f[5]);
                __half2 h3 = __floats2half2_rn(f[6], f[7]);
                *(uint4*)&sA[rr * 72 + c8] = make_uint4(*(unsigned*)&h0, *(unsigned*)&h1,
                                                        *(unsigned*)&h2, *(unsigned*)&h3);
            }
        }
        __syncthreads();

        float acc[8][4];
#pragma unroll
        for (int j = 0; j < 8; j++)
#pragma unroll
            for (int i = 0; i < 4; i++) acc[j][i] = 0.f;

#pragma unroll
        for (int kk = 0; kk < 4; kk++) {
            int arow = mrow + (sub & 1) * 8 + lr;
            int acol = kk * 16 + (sub >> 1) * 8;
            unsigned a0, a1, a2, a3;
            ldsm_x4(a0, a1, a2, a3, aBase + (unsigned)(arow * 72 + acol) * 2);
#pragma unroll
            for (int jj = 0; jj < 4; jj++) {
                int brow = kk * 16 + (sub & 1) * 8 + lr;
                int bcol = (jj * 2 + (sub >> 1)) * 8;
                unsigned b0, b1, b2, b3;
                ldsm_x4t(b0, b1, b2, b3, wBase + (unsigned)(brow * 72 + bcol) * 2);
                mma16816(acc[jj * 2],     a0, a1, a2, a3, b0, b1);
                mma16816(acc[jj * 2 + 1], a0, a1, a2, a3, b2, b3);
            }
        }

        // epilogue: c0/c1 -> row g1, c2/c3 -> row g2 = g1+8; cols j*8 + 2*(lane&3)
        int g1 = r0 + mrow + (lane >> 2);
        int g2 = g1 + 8;
        int cq = (lane & 3) * 2;
        float dv1 = (g1 < NN) ? g_dinv[g1] : 0.f;
        float dv2 = (g2 < NN) ? g_dinv[g2] : 0.f;
#pragma unroll
        for (int j = 0; j < 8; j++) {
            if (g1 < NN) {
                __half2 h = __floats2half2_rn(acc[j][0] * dv1, acc[j][1] * dv1);
                *(__half2*)&g_bufA[(size_t)g1 * 64 + j * 8 + cq] = h;
            }
            if (g2 < NN) {
                __half2 h = __floats2half2_rn(acc[j][2] * dv2, acc[j][3] * dv2);
                *(__half2*)&g_bufA[(size_t)g2 * 64 + j * 8 + cq] = h;
            }
        }
    }
}

__global__ void __launch_bounds__(128) k_gemm1(const float* __restrict__ x,
                                               const float* __restrict__ W) {
    gemm_core(x, W, 0);
}
__global__ void __launch_bounds__(128) k_gemm23(const float* __restrict__ W, int l) {
    gemm_core(0, W, l);
}

// ---------------- binned aggregation (warp per destination) -> fp16 bufC ----------------
// bufC[c] = dinv[c] * ( sum_e w_e * bufA'[src_e] + bufA'[c] ) + bias
__global__ void __launch_bounds__(256) k_agg(const float* __restrict__ bias) {
    int warp = threadIdx.x >> 5;
    int lane = threadIdx.x & 31;
    int c = blockIdx.x * 8 + warp;          // NN % 8 == 0
    int half = lane >> 4;
    int q = lane & 15;
    int cnt = g_cursor[c];
    const int2* __restrict__ pay = g_pay + (size_t)c * SLOT;

    const uint2* __restrict__ A2 = (const uint2*)g_bufA;   // 16 uint2 per 64-feat row

    float4 acc = make_float4(0.f, 0.f, 0.f, 0.f);
    for (int e = half; e < cnt; e += 2) {
        int2 p = __ldg(&pay[e]);
        uint2 r = __ldg(&A2[(size_t)p.x * 16 + q]);
        float n = __int_as_float(p.y);
        float2 f0 = __half22float2(*(__half2*)&r.x);
        float2 f1 = __half22float2(*(__half2*)&r.y);
        acc.x += f0.x * n; acc.y += f0.y * n;
        acc.z += f1.x * n; acc.w += f1.y * n;
    }
    acc.x += __shfl_xor_sync(0xFFFFFFFFu, acc.x, 16);
    acc.y += __shfl_xor_sync(0xFFFFFFFFu, acc.y, 16);
    acc.z += __shfl_xor_sync(0xFFFFFFFFu, acc.z, 16);
    acc.w += __shfl_xor_sync(0xFFFFFFFFu, acc.w, 16);

    if (half == 0) {
        float dv = g_dinv[c];
        uint2 sr = __ldg(&A2[(size_t)c * 16 + q]);         // bufA'[c] = h[c]*dinv[c]
        float2 s0 = __half22float2(*(__half2*)&sr.x);
        float2 s1 = __half22float2(*(__half2*)&sr.y);
        float4 b = *(const float4*)(bias + q * 4);
        __half2 h0 = __floats2half2_rn((acc.x + s0.x) * dv + b.x,
                                       (acc.y + s0.y) * dv + b.y);
        __half2 h1 = __floats2half2_rn((acc.z + s1.x) * dv + b.z,
                                       (acc.w + s1.y) * dv + b.w);
        *(uint2*)&g_bufC[(size_t)c * 64 + q * 4] =
            make_uint2(*(unsigned*)&h0, *(unsigned*)&h1);
    }
}

// ---------------- layer-3 aggregation + BN3 + global_add_pool ----------------
// pooled[batch[c]] += bn3( dinv[c]*(edge_sum + self) + bias )
__global__ void __launch_bounds__(256) k_agg3(const float* __restrict__ bias,
                                              const int* __restrict__ batch) {
    __shared__ float sacc[64];
    __shared__ int sbatch[8];
    int warp = threadIdx.x >> 5;
    int lane = threadIdx.x & 31;
    int c = blockIdx.x * 8 + warp;          // NN % 8 == 0
    int half = lane >> 4;
    int q = lane & 15;
    int cnt = g_cursor[c];
    const int2* __restrict__ pay = g_pay + (size_t)c * SLOT;
    const uint2* __restrict__ A2 = (const uint2*)g_bufA;

    if (threadIdx.x < 64) sacc[threadIdx.x] = 0.f;
    if (lane == 0) sbatch[warp] = batch[c];

    float4 acc = make_float4(0.f, 0.f, 0.f, 0.f);
    for (int e = half; e < cnt; e += 2) {
        int2 p = __ldg(&pay[e]);
        uint2 r = __ldg(&A2[(size_t)p.x * 16 + q]);
        float n = __int_as_float(p.y);
        float2 f0 = __half22float2(*(__half2*)&r.x);
        float2 f1 = __half22float2(*(__half2*)&r.y);
        acc.x += f0.x * n; acc.y += f0.y * n;
        acc.z += f1.x * n; acc.w += f1.y * n;
    }
    acc.x += __shfl_xor_sync(0xFFFFFFFFu, acc.x, 16);
    acc.y += __shfl_xor_sync(0xFFFFFFFFu, acc.y, 16);
    acc.z += __shfl_xor_sync(0xFFFFFFFFu, acc.z, 16);
    acc.w += __shfl_xor_sync(0xFFFFFFFFu, acc.w, 16);

    __syncthreads();
    bool uni = true;
#pragma unroll
    for (int i = 1; i < 8; i++) uni &= (sbatch[i] == sbatch[0]);

    if (half == 0) {
        float dv = g_dinv[c];
        uint2 sr = __ldg(&A2[(size_t)c * 16 + q]);
        float2 s0 = __half22float2(*(__half2*)&sr.x);
        float2 s1 = __half22float2(*(__half2*)&sr.y);
        float4 b = *(const float4*)(bias + q * 4);
        float4 sc = *(const float4*)&g_bnsc[2][q * 4];
        float4 sh = *(const float4*)&g_bnsh[2][q * 4];
        float o0 = ((acc.x + s0.x) * dv + b.x) * sc.x + sh.x;
        float o1 = ((acc.y + s0.y) * dv + b.y) * sc.y + sh.y;
        float o2 = ((acc.z + s1.x) * dv + b.z) * sc.z + sh.z;
        float o3 = ((acc.w + s1.y) * dv + b.w) * sc.w + sh.w;
        if (uni) {
            atomicAdd(&sacc[q * 4 + 0], o0);
            atomicAdd(&sacc[q * 4 + 1], o1);
            atomicAdd(&sacc[q * 4 + 2], o2);
            atomicAdd(&sacc[q * 4 + 3], o3);
        } else {
            int bg = sbatch[warp];
            atomicAdd(&g_pooled[bg * 64 + q * 4 + 0], o0);
            atomicAdd(&g_pooled[bg * 64 + q * 4 + 1], o1);
            atomicAdd(&g_pooled[bg * 64 + q * 4 + 2], o2);
            atomicAdd(&g_pooled[bg * 64 + q * 4 + 3], o3);
        }
    }
    __syncthreads();
    if (uni && threadIdx.x < 64)
        atomicAdd(&g_pooled[sbatch[0] * 64 + threadIdx.x], sacc[threadIdx.x]);
}

// ---------------- FC: out[g] = relu(pooled[g]) . Wfc + bfc ----------------
__global__ void k_fc(const float* __restrict__ Wfc, const float* __restrict__ bfc,
                     float* __restrict__ out) {
    int g = threadIdx.x;  // 128
    float acc = 0.f;
#pragma unroll
    for (int k = 0; k < 64; k++)
        acc += fmaxf(g_pooled[g * 64 + k], 0.f) * Wfc[k];
    out[g] = acc + bfc[0];
}

// ---------------- launch ----------------
extern "C" void kernel_launch(void* const* d_in, const int* in_sizes, int n_in,
                              void* d_out, int out_size) {
    const float* x     = (const float*)d_in[0];
    const int*   ei    = (const int*)d_in[1];
    const int*   row   = ei;
    const int*   col   = ei + EE;
    const float* ew    = (const float*)d_in[2];
    const int*   batch = (const int*)d_in[3];
    const float* W1 = (const float*)d_in[4];
    const float* b1 = (const float*)d_in[5];
    const float* W2 = (const float*)d_in[6];
    const float* b2 = (const float*)d_in[7];
    const float* W3 = (const float*)d_in[8];
    const float* b3 = (const float*)d_in[9];
    const float* Wfc = (const float*)d_in[10];
    const float* bfc = (const float*)d_in[11];

    BNParams bp;
    for (int i = 0; i < 12; i++) bp.p[i] = (const float*)d_in[12 + i];

    int nb_n = (NN + 255) / 256;            // 391
    int nb_e = (EE + 255) / 256;            // 6250
    int nb_gemm = (NN + 255) / 256;         // 391 (4 x 64-row tiles per block)
    int nb_agg = NN / 8;                    // 12500

    // CSR-free build
    k_prep<<<nb_n, 256>>>(bp);
    k_degw<<<nb_e, 256>>>(col, ew);
    k_scatter<<<nb_e, 256>>>(row, col, ew);

    // layer 1 (fp32 input, no act)
    k_gemm1<<<nb_gemm, 128>>>(x, W1);
    k_agg<<<nb_agg, 256>>>(b1);
    // layer 2 (relu + bn1 on fp16 input)
    k_gemm23<<<nb_gemm, 128>>>(W2, 0);
    k_agg<<<nb_agg, 256>>>(b2);
    // layer 3 (relu + bn2 on fp16 input) + fused BN3/pool
    k_gemm23<<<nb_gemm, 128>>>(W3, 1);
    k_agg3<<<nb_agg, 256>>>(b3, batch);

    // fc
    k_fc<<<1, 128>>>(Wfc, bfc, (float*)d_out);
}

// round 13
// speedup vs baseline: 1.5409x; 1.0261x over previous
#include <cuda_runtime.h>
#include <cuda_fp16.h>
#include <stdint.h>

#define NN 100000
#define EE 1600000
#define GG 128
#define SLOT 64  // payload slots per destination (Poisson(16) max << 64)

// ---------------- scratch (static device globals; no allocation) ----------------
__device__ __align__(16) float g_dinv[NN];
__device__ __align__(16) int   g_cursor[NN];
__device__ __align__(16) int2  g_pay[(size_t)NN * SLOT];   // {src, w-as-bits} binned by dest
__device__ __align__(16) __half g_bufA[(size_t)NN * 64];   // h*dinv (gemm output, fp16)
__device__ __align__(16) __half g_bufC[(size_t)NN * 64];   // ACTIVATED conv output layers 1-2 (fp16)
__device__ __align__(16) float g_pooled[GG * 64];
__device__ __align__(16) float g_bnsc[3][64];
__device__ __align__(16) float g_bnsh[3][64];

struct BNParams { const float* p[12]; };  // (gamma,beta,mean,var) x 3 layers

// ---------------- mma helpers ----------------
__device__ __forceinline__ unsigned s2u(const void* p) {
    unsigned a;
    asm("{ .reg .u64 t; cvta.to.shared.u64 t, %1; cvt.u32.u64 %0, t; }" : "=r"(a) : "l"(p));
    return a;
}
__device__ __forceinline__ void ldsm_x4(unsigned& r0, unsigned& r1, unsigned& r2, unsigned& r3,
                                        unsigned addr) {
    asm volatile("ldmatrix.sync.aligned.m8n8.x4.shared.b16 {%0,%1,%2,%3}, [%4];"
                 : "=r"(r0), "=r"(r1), "=r"(r2), "=r"(r3) : "r"(addr));
}
__device__ __forceinline__ void ldsm_x4t(unsigned& r0, unsigned& r1, unsigned& r2, unsigned& r3,
                                         unsigned addr) {
    asm volatile("ldmatrix.sync.aligned.m8n8.x4.trans.shared.b16 {%0,%1,%2,%3}, [%4];"
                 : "=r"(r0), "=r"(r1), "=r"(r2), "=r"(r3) : "r"(addr));
}
__device__ __forceinline__ void mma16816(float* c, unsigned a0, unsigned a1, unsigned a2,
                                         unsigned a3, unsigned b0, unsigned b1) {
    asm volatile(
        "mma.sync.aligned.m16n8k16.row.col.f32.f16.f16.f32 "
        "{%0,%1,%2,%3}, {%4,%5,%6,%7}, {%8,%9}, {%0,%1,%2,%3};"
        : "+f"(c[0]), "+f"(c[1]), "+f"(c[2]), "+f"(c[3])
        : "r"(a0), "r"(a1), "r"(a2), "r"(a3), "r"(b0), "r"(b1));
}

// ---------------- prep: zero cursor/pooled, BN consts ----------------
__global__ void k_prep(BNParams bp) {
    int i = blockIdx.x * blockDim.x + threadIdx.x;
    if (i < NN) g_cursor[i] = 0;
    if (i < GG * 64) g_pooled[i] = 0.0f;
    if (i < 3 * 64) {
        int l = i >> 6, f = i & 63;
        const float* ga = bp.p[l * 4 + 0];
        const float* be = bp.p[l * 4 + 1];
        const float* mn = bp.p[l * 4 + 2];
        const float* va = bp.p[l * 4 + 3];
        float sc = ga[f] * rsqrtf(va[f] + 1e-5f);
        g_bnsc[l][f] = sc;
        g_bnsh[l][f] = be[f] - mn[f] * sc;
    }
}

// bin edges by destination; payload = {src, w}
__global__ void k_scatter(const int* __restrict__ row, const int* __restrict__ col,
                          const float* __restrict__ w) {
    int e = blockIdx.x * blockDim.x + threadIdx.x;
    if (e >= EE) return;
    int r = row[e];
    int c = col[e];
    int pos = atomicAdd(&g_cursor[c], 1);
    if (pos > SLOT - 1) pos = SLOT - 1;                 // unreachable; memory safety only
    g_pay[(size_t)c * SLOT + pos] = make_int2(r, __float_as_int(w[e]));
}

// weighted degree from bins -> dinv (replaces the 1.6M-atomic degw pass)
__global__ void k_fin() {
    int c = blockIdx.x * blockDim.x + threadIdx.x;
    if (c >= NN) return;
    int cnt = g_cursor[c];
    if (cnt > SLOT) cnt = SLOT;
    const int2* __restrict__ pay = g_pay + (size_t)c * SLOT;
    float s = 0.f;
    for (int e = 0; e < cnt; e++) s += __int_as_float(__ldg(&pay[e]).y);
    g_dinv[c] = rsqrtf(1.0f + s);
}

// ---------------- tensor-core GEMM: bufA = (in @ W) * dinv[row]  (fp16 out) ----------
// 128 threads / 4 warps; block covers 2 tiles of 64 rows; W staged once.
// in32 != nullptr: fp32 input (layer 1). Else: fp16 activated input from g_bufC (raw copy).
__device__ __forceinline__ void gemm_core(const float* in32, const float* W) {
    __shared__ __align__(16) __half sA[64 * 72];   // row r at r*72 (144B stride, 16B aligned)
    __shared__ __align__(16) __half sW[64 * 72];   // k row at k*72
    int t = threadIdx.x;

    // stage W (fp32 -> fp16) once
    const float4* W4 = (const float4*)W;
#pragma unroll
    for (int j = 0; j < 8; j++) {
        int idx = t + 128 * j;            // 1024 float4 = 64x64 fp32
        float4 v = W4[idx];
        int k = idx >> 4, c4 = idx & 15;
        __half2 h0 = __floats2half2_rn(v.x, v.y);
        __half2 h1 = __floats2half2_rn(v.z, v.w);
        *(uint2*)&sW[k * 72 + c4 * 4] = make_uint2(*(unsigned*)&h0, *(unsigned*)&h1);
    }

    int warp = t >> 5, lane = t & 31;
    int mrow = warp * 16;
    unsigned aBase = s2u(sA), wBase = s2u(sW);
    int sub = lane >> 3, lr = lane & 7;

#pragma unroll
    for (int tile = 0; tile < 2; tile++) {
        int r0 = (blockIdx.x * 2 + tile) * 64;
        __syncthreads();   // W staged (1st iter) / all warps done reading sA (2nd iter)

        if (in32 != 0) {
#pragma unroll
            for (int j = 0; j < 8; j++) {
                int idx = t + 128 * j;
                int rr = idx >> 4, c4 = idx & 15;
                int gr = r0 + rr;
                float4 v = make_float4(0.f, 0.f, 0.f, 0.f);
                if (gr < NN) v = *(const float4*)(in32 + (size_t)gr * 64 + c4 * 4);
                __half2 h0 = __floats2half2_rn(v.x, v.y);
                __half2 h1 = __floats2half2_rn(v.z, v.w);
                *(uint2*)&sA[rr * 72 + c4 * 4] = make_uint2(*(unsigned*)&h0, *(unsigned*)&h1);
            }
        } else {
            const __half* in = g_bufC;
#pragma unroll
            for (int j = 0; j < 4; j++) {
                int idx = t + 128 * j;
                int rr = idx >> 3, c8 = (idx & 7) * 8;
                int gr = r0 + rr;
                uint4 v = make_uint4(0, 0, 0, 0);
                if (gr < NN) v = *(const uint4*)(in + (size_t)gr * 64 + c8);
                *(uint4*)&sA[rr * 72 + c8] = v;
            }
        }
        __syncthreads();

        float acc[8][4];
#pragma unroll
        for (int j = 0; j < 8; j++)
#pragma unroll
            for (int i = 0; i < 4; i++) acc[j][i] = 0.f;

#pragma unroll
        for (int kk = 0; kk < 4; kk++) {
            int arow = mrow + (sub & 1) * 8 + lr;
            int acol = kk * 16 + (sub >> 1) * 8;
            unsigned a0, a1, a2, a3;
            ldsm_x4(a0, a1, a2, a3, aBase + (unsigned)(arow * 72 + acol) * 2);
#pragma unroll
            for (int jj = 0; jj < 4; jj++) {
                int brow = kk * 16 + (sub & 1) * 8 + lr;
                int bcol = (jj * 2 + (sub >> 1)) * 8;
                unsigned b0, b1, b2, b3;
                ldsm_x4t(b0, b1, b2, b3, wBase + (unsigned)(brow * 72 + bcol) * 2);
                mma16816(acc[jj * 2],     a0, a1, a2, a3, b0, b1);
                mma16816(acc[jj * 2 + 1], a0, a1, a2, a3, b2, b3);
            }
        }

        int g1 = r0 + mrow + (lane >> 2);
        int g2 = g1 + 8;
        int cq = (lane & 3) * 2;
        float dv1 = (g1 < NN) ? g_dinv[g1] : 0.f;
        float dv2 = (g2 < NN) ? g_dinv[g2] : 0.f;
#pragma unroll
        for (int j = 0; j < 8; j++) {
            if (g1 < NN) {
                __half2 h = __floats2half2_rn(acc[j][0] * dv1, acc[j][1] * dv1);
                *(__half2*)&g_bufA[(size_t)g1 * 64 + j * 8 + cq] = h;
            }
            if (g2 < NN) {
                __half2 h = __floats2half2_rn(acc[j][2] * dv2, acc[j][3] * dv2);
                *(__half2*)&g_bufA[(size_t)g2 * 64 + j * 8 + cq] = h;
            }
        }
    }
}

__global__ void __launch_bounds__(128) k_gemm1(const float* __restrict__ x,
                                               const float* __restrict__ W) {
    gemm_core(x, W);
}
__global__ void __launch_bounds__(128) k_gemm23(const float* __restrict__ W) {
    gemm_core(0, W);
}

// ---------------- binned aggregation (warp per destination) -> activated fp16 bufC ----------
// bufC[c] = relu( dinv[c]*(edge_sum + self) + bias ) * bnsc[l] + bnsh[l]
__global__ void __launch_bounds__(256) k_agg(const float* __restrict__ bias, int l) {
    int warp = threadIdx.x >> 5;
    int lane = threadIdx.x & 31;
    int c = blockIdx.x * 8 + warp;          // NN % 8 == 0
    int half = lane >> 4;
    int q = lane & 15;
    int cnt = g_cursor[c];
    if (cnt > SLOT) cnt = SLOT;
    const int2* __restrict__ pay = g_pay + (size_t)c * SLOT;

    const uint2* __restrict__ A2 = (const uint2*)g_bufA;   // 16 uint2 per 64-feat row

    float4 acc = make_float4(0.f, 0.f, 0.f, 0.f);
    for (int e = half; e < cnt; e += 2) {
        int2 p = __ldg(&pay[e]);
        uint2 r = __ldg(&A2[(size_t)p.x * 16 + q]);
        float n = __int_as_float(p.y);
        float2 f0 = __half22float2(*(__half2*)&r.x);
        float2 f1 = __half22float2(*(__half2*)&r.y);
        acc.x += f0.x * n; acc.y += f0.y * n;
        acc.z += f1.x * n; acc.w += f1.y * n;
    }
    acc.x += __shfl_xor_sync(0xFFFFFFFFu, acc.x, 16);
    acc.y += __shfl_xor_sync(0xFFFFFFFFu, acc.y, 16);
    acc.z += __shfl_xor_sync(0xFFFFFFFFu, acc.z, 16);
    acc.w += __shfl_xor_sync(0xFFFFFFFFu, acc.w, 16);

    if (half == 0) {
        float dv = g_dinv[c];
        uint2 sr = __ldg(&A2[(size_t)c * 16 + q]);         // bufA'[c] = h[c]*dinv[c]
        float2 s0 = __half22float2(*(__half2*)&sr.x);
        float2 s1 = __half22float2(*(__half2*)&sr.y);
        float4 b = *(const float4*)(bias + q * 4);
        float4 sc = *(const float4*)&g_bnsc[l][q * 4];
        float4 sh = *(const float4*)&g_bnsh[l][q * 4];
        float o0 = fmaxf((acc.x + s0.x) * dv + b.x, 0.f) * sc.x + sh.x;
        float o1 = fmaxf((acc.y + s0.y) * dv + b.y, 0.f) * sc.y + sh.y;
        float o2 = fmaxf((acc.z + s1.x) * dv + b.z, 0.f) * sc.z + sh.z;
        float o3 = fmaxf((acc.w + s1.y) * dv + b.w, 0.f) * sc.w + sh.w;
        __half2 h0 = __floats2half2_rn(o0, o1);
        __half2 h1 = __floats2half2_rn(o2, o3);
        *(uint2*)&g_bufC[(size_t)c * 64 + q * 4] =
            make_uint2(*(unsigned*)&h0, *(unsigned*)&h1);
    }
}

// ---------------- layer-3 aggregation + BN3 + global_add_pool ----------------
__global__ void __launch_bounds__(256) k_agg3(const float* __restrict__ bias,
                                              const int* __restrict__ batch) {
    __shared__ float sacc[64];
    __shared__ int sbatch[8];
    int warp = threadIdx.x >> 5;
    int lane = threadIdx.x & 31;
    int c = blockIdx.x * 8 + warp;          // NN % 8 == 0
    int half = lane >> 4;
    int q = lane & 15;
    int cnt = g_cursor[c];
    if (cnt > SLOT) cnt = SLOT;
    const int2* __restrict__ pay = g_pay + (size_t)c * SLOT;
    const uint2* __restrict__ A2 = (const uint2*)g_bufA;

    if (threadIdx.x < 64) sacc[threadIdx.x] = 0.f;
    if (lane == 0) sbatch[warp] = batch[c];

    float4 acc = make_float4(0.f, 0.f, 0.f, 0.f);
    for (int e = half; e < cnt; e += 2) {
        int2 p = __ldg(&pay[e]);
        uint2 r = __ldg(&A2[(size_t)p.x * 16 + q]);
        float n = __int_as_float(p.y);
        float2 f0 = __half22float2(*(__half2*)&r.x);
        float2 f1 = __half22float2(*(__half2*)&r.y);
        acc.x += f0.x * n; acc.y += f0.y * n;
        acc.z += f1.x * n; acc.w += f1.y * n;
    }
    acc.x += __shfl_xor_sync(0xFFFFFFFFu, acc.x, 16);
    acc.y += __shfl_xor_sync(0xFFFFFFFFu, acc.y, 16);
    acc.z += __shfl_xor_sync(0xFFFFFFFFu, acc.z, 16);
    acc.w += __shfl_xor_sync(0xFFFFFFFFu, acc.w, 16);

    __syncthreads();
    bool uni = true;
#pragma unroll
    for (int i = 1; i < 8; i++) uni &= (sbatch[i] == sbatch[0]);

    if (half == 0) {
        float dv = g_dinv[c];
        uint2 sr = __ldg(&A2[(size_t)c * 16 + q]);
        float2 s0 = __half22float2(*(__half2*)&sr.x);
        float2 s1 = __half22float2(*(__half2*)&sr.y);
        float4 b = *(const float4*)(bias + q * 4);
        float4 sc = *(const float4*)&g_bnsc[2][q * 4];
        float4 sh = *(const float4*)&g_bnsh[2][q * 4];
        float o0 = ((acc.x + s0.x) * dv + b.x) * sc.x + sh.x;
        float o1 = ((acc.y + s0.y) * dv + b.y) * sc.y + sh.y;
        float o2 = ((acc.z + s1.x) * dv + b.z) * sc.z + sh.z;
        float o3 = ((acc.w + s1.y) * dv + b.w) * sc.w + sh.w;
        if (uni) {
            atomicAdd(&sacc[q * 4 + 0], o0);
            atomicAdd(&sacc[q * 4 + 1], o1);
            atomicAdd(&sacc[q * 4 + 2], o2);
            atomicAdd(&sacc[q * 4 + 3], o3);
        } else {
            int bg = sbatch[warp];
            atomicAdd(&g_pooled[bg * 64 + q * 4 + 0], o0);
            atomicAdd(&g_pooled[bg * 64 + q * 4 + 1], o1);
            atomicAdd(&g_pooled[bg * 64 + q * 4 + 2], o2);
            atomicAdd(&g_pooled[bg * 64 + q * 4 + 3], o3);
        }
    }
    __syncthreads();
    if (uni && threadIdx.x < 64)
        atomicAdd(&g_pooled[sbatch[0] * 64 + threadIdx.x], sacc[threadIdx.x]);
}

// ---------------- FC: out[g] = relu(pooled[g]) . Wfc + bfc ----------------
__global__ void k_fc(const float* __restrict__ Wfc, const float* __restrict__ bfc,
                     float* __restrict__ out) {
    int g = threadIdx.x;  // 128
    float acc = 0.f;
#pragma unroll
    for (int k = 0; k < 64; k++)
        acc += fmaxf(g_pooled[g * 64 + k], 0.f) * Wfc[k];
    out[g] = acc + bfc[0];
}

// ---------------- launch ----------------
extern "C" void kernel_launch(void* const* d_in, const int* in_sizes, int n_in,
                              void* d_out, int out_size) {
    const float* x     = (const float*)d_in[0];
    const int*   ei    = (const int*)d_in[1];
    const int*   row   = ei;
    const int*   col   = ei + EE;
    const float* ew    = (const float*)d_in[2];
    const int*   batch = (const int*)d_in[3];
    const float* W1 = (const float*)d_in[4];
    const float* b1 = (const float*)d_in[5];
    const float* W2 = (const float*)d_in[6];
    const float* b2 = (const float*)d_in[7];
    const float* W3 = (const float*)d_in[8];
    const float* b3 = (const float*)d_in[9];
    const float* Wfc = (const float*)d_in[10];
    const float* bfc = (const float*)d_in[11];

    BNParams bp;
    for (int i = 0; i < 12; i++) bp.p[i] = (const float*)d_in[12 + i];

    int nb_n = (NN + 255) / 256;            // 391
    int nb_e = (EE + 255) / 256;            // 6250
    int nb_gemm = (NN + 127) / 128;         // 782 (2 x 64-row tiles per block)
    int nb_agg = NN / 8;                    // 12500

    // build: bin edges, then derive dinv from bins
    k_prep<<<nb_n, 256>>>(bp);
    k_scatter<<<nb_e, 256>>>(row, col, ew);
    k_fin<<<nb_n, 256>>>();

    // layer 1 (fp32 input)
    k_gemm1<<<nb_gemm, 128>>>(x, W1);
    k_agg<<<nb_agg, 256>>>(b1, 0);
    // layer 2 (activated fp16 input)
    k_gemm23<<<nb_gemm, 128>>>(W2);
    k_agg<<<nb_agg, 256>>>(b2, 1);
    // layer 3 + fused BN3/pool
    k_gemm23<<<nb_gemm, 128>>>(W3);
    k_agg3<<<nb_agg, 256>>>(b3, batch);

    // fc
    k_fc<<<1, 128>>>(Wfc, bfc, (float*)d_out);
}

// round 14
// speedup vs baseline: 1.5444x; 1.0023x over previous
#include <cuda_runtime.h>
#include <cuda_fp16.h>
#include <stdint.h>

#define NN 100000
#define EE 1600000
#define GG 128
#define SLOT 64  // payload slots per destination (Poisson(16) max << 64)

// ---------------- scratch (static device globals; no allocation) ----------------
__device__ __align__(16) float g_dinv[NN];
__device__ __align__(16) int   g_cursor[NN];
__device__ __align__(16) int2  g_pay[(size_t)NN * SLOT];   // {src, w-as-bits} binned by dest
__device__ __align__(16) __half g_bufA[(size_t)NN * 64];   // h*dinv (gemm output, fp16)
__device__ __align__(16) __half g_bufC[(size_t)NN * 64];   // ACTIVATED conv output layers 1-2 (fp16)
__device__ __align__(16) float g_pooled[GG * 64];
__device__ __align__(16) float g_bnsc[3][64];
__device__ __align__(16) float g_bnsh[3][64];

struct BNParams { const float* p[12]; };  // (gamma,beta,mean,var) x 3 layers

// ---------------- mma helpers ----------------
__device__ __forceinline__ unsigned s2u(const void* p) {
    unsigned a;
    asm("{ .reg .u64 t; cvta.to.shared.u64 t, %1; cvt.u32.u64 %0, t; }" : "=r"(a) : "l"(p));
    return a;
}
__device__ __forceinline__ void ldsm_x4(unsigned& r0, unsigned& r1, unsigned& r2, unsigned& r3,
                                        unsigned addr) {
    asm volatile("ldmatrix.sync.aligned.m8n8.x4.shared.b16 {%0,%1,%2,%3}, [%4];"
                 : "=r"(r0), "=r"(r1), "=r"(r2), "=r"(r3) : "r"(addr));
}
__device__ __forceinline__ void ldsm_x4t(unsigned& r0, unsigned& r1, unsigned& r2, unsigned& r3,
                                         unsigned addr) {
    asm volatile("ldmatrix.sync.aligned.m8n8.x4.trans.shared.b16 {%0,%1,%2,%3}, [%4];"
                 : "=r"(r0), "=r"(r1), "=r"(r2), "=r"(r3) : "r"(addr));
}
__device__ __forceinline__ void mma16816(float* c, unsigned a0, unsigned a1, unsigned a2,
                                         unsigned a3, unsigned b0, unsigned b1) {
    asm volatile(
        "mma.sync.aligned.m16n8k16.row.col.f32.f16.f16.f32 "
        "{%0,%1,%2,%3}, {%4,%5,%6,%7}, {%8,%9}, {%0,%1,%2,%3};"
        : "+f"(c[0]), "+f"(c[1]), "+f"(c[2]), "+f"(c[3])
        : "r"(a0), "r"(a1), "r"(a2), "r"(a3), "r"(b0), "r"(b1));
}

// ---------------- prep: zero cursor/pooled, BN consts ----------------
__global__ void k_prep(BNParams bp) {
    int i = blockIdx.x * blockDim.x + threadIdx.x;
    if (i < NN) g_cursor[i] = 0;
    if (i < GG * 64) g_pooled[i] = 0.0f;
    if (i < 3 * 64) {
        int l = i >> 6, f = i & 63;
        const float* ga = bp.p[l * 4 + 0];
        const float* be = bp.p[l * 4 + 1];
        const float* mn = bp.p[l * 4 + 2];
        const float* va = bp.p[l * 4 + 3];
        float sc = ga[f] * rsqrtf(va[f] + 1e-5f);
        g_bnsc[l][f] = sc;
        g_bnsh[l][f] = be[f] - mn[f] * sc;
    }
}

// bin edges by destination; payload = {src, w}
__global__ void k_scatter(const int* __restrict__ row, const int* __restrict__ col,
                          const float* __restrict__ w) {
    int e = blockIdx.x * blockDim.x + threadIdx.x;
    if (e >= EE) return;
    int r = row[e];
    int c = col[e];
    int pos = atomicAdd(&g_cursor[c], 1);
    if (pos > SLOT - 1) pos = SLOT - 1;                 // unreachable; memory safety only
    g_pay[(size_t)c * SLOT + pos] = make_int2(r, __float_as_int(w[e]));
}

// weighted degree from bins -> dinv (replaces a full atomic pass over edges)
__global__ void k_fin() {
    int c = blockIdx.x * blockDim.x + threadIdx.x;
    if (c >= NN) return;
    int cnt = g_cursor[c];
    if (cnt > SLOT) cnt = SLOT;
    const int2* __restrict__ pay = g_pay + (size_t)c * SLOT;
    float s = 0.f;
    for (int e = 0; e < cnt; e++) s += __int_as_float(__ldg(&pay[e]).y);
    g_dinv[c] = rsqrtf(1.0f + s);
}

// ---------------- tensor-core GEMM: bufA = (in @ W) * dinv[row]  (fp16 out) ----------
// 256 threads / 8 warps; one 128-row x 64-col tile per block; warp w owns rows [16w,16w+16).
// in32 != nullptr: fp32 input (layer 1). Else: fp16 activated input from g_bufC (raw copy).
__device__ __forceinline__ void gemm_core(const float* in32, const float* W) {
    __shared__ __align__(16) __half sA[128 * 72];  // row r at r*72 (144B stride, 16B aligned)
    __shared__ __align__(16) __half sW[64 * 72];   // k row at k*72
    int t = threadIdx.x;   // 256
    int r0 = blockIdx.x * 128;

    // stage W (fp32 -> fp16)
    const float4* W4 = (const float4*)W;
#pragma unroll
    for (int j = 0; j < 4; j++) {
        int idx = t + 256 * j;            // 1024 float4 = 64x64 fp32
        float4 v = W4[idx];
        int k = idx >> 4, c4 = idx & 15;
        __half2 h0 = __floats2half2_rn(v.x, v.y);
        __half2 h1 = __floats2half2_rn(v.z, v.w);
        *(uint2*)&sW[k * 72 + c4 * 4] = make_uint2(*(unsigned*)&h0, *(unsigned*)&h1);
    }

    // stage input rows
    if (in32 != 0) {
#pragma unroll
        for (int j = 0; j < 8; j++) {
            int idx = t + 256 * j;         // 2048 float4 = 128 rows x 16 float4
            int rr = idx >> 4, c4 = idx & 15;
            int gr = r0 + rr;
            float4 v = make_float4(0.f, 0.f, 0.f, 0.f);
            if (gr < NN) v = *(const float4*)(in32 + (size_t)gr * 64 + c4 * 4);
            __half2 h0 = __floats2half2_rn(v.x, v.y);
            __half2 h1 = __floats2half2_rn(v.z, v.w);
            *(uint2*)&sA[rr * 72 + c4 * 4] = make_uint2(*(unsigned*)&h0, *(unsigned*)&h1);
        }
    } else {
        const __half* in = g_bufC;
#pragma unroll
        for (int j = 0; j < 4; j++) {
            int idx = t + 256 * j;         // 1024 uint4 = 128 rows x 8 uint4
            int rr = idx >> 3, c8 = (idx & 7) * 8;
            int gr = r0 + rr;
            uint4 v = make_uint4(0, 0, 0, 0);
            if (gr < NN) v = *(const uint4*)(in + (size_t)gr * 64 + c8);
            *(uint4*)&sA[rr * 72 + c8] = v;
        }
    }
    __syncthreads();

    int warp = t >> 5, lane = t & 31;
    int mrow = warp * 16;
    unsigned aBase = s2u(sA), wBase = s2u(sW);
    int sub = lane >> 3, lr = lane & 7;

    float acc[8][4];
#pragma unroll
    for (int j = 0; j < 8; j++)
#pragma unroll
        for (int i = 0; i < 4; i++) acc[j][i] = 0.f;

#pragma unroll
    for (int kk = 0; kk < 4; kk++) {
        int arow = mrow + (sub & 1) * 8 + lr;
        int acol = kk * 16 + (sub >> 1) * 8;
        unsigned a0, a1, a2, a3;
        ldsm_x4(a0, a1, a2, a3, aBase + (unsigned)(arow * 72 + acol) * 2);
#pragma unroll
        for (int jj = 0; jj < 4; jj++) {
            int brow = kk * 16 + (sub & 1) * 8 + lr;
            int bcol = (jj * 2 + (sub >> 1)) * 8;
            unsigned b0, b1, b2, b3;
            ldsm_x4t(b0, b1, b2, b3, wBase + (unsigned)(brow * 72 + bcol) * 2);
            mma16816(acc[jj * 2],     a0, a1, a2, a3, b0, b1);
            mma16816(acc[jj * 2 + 1], a0, a1, a2, a3, b2, b3);
        }
    }

    // epilogue: c0/c1 -> row g1, c2/c3 -> row g2 = g1+8; cols j*8 + 2*(lane&3)
    int g1 = r0 + mrow + (lane >> 2);
    int g2 = g1 + 8;
    int cq = (lane & 3) * 2;
    float dv1 = (g1 < NN) ? g_dinv[g1] : 0.f;
    float dv2 = (g2 < NN) ? g_dinv[g2] : 0.f;
#pragma unroll
    for (int j = 0; j < 8; j++) {
        if (g1 < NN) {
            __half2 h = __floats2half2_rn(acc[j][0] * dv1, acc[j][1] * dv1);
            *(__half2*)&g_bufA[(size_t)g1 * 64 + j * 8 + cq] = h;
        }
        if (g2 < NN) {
            __half2 h = __floats2half2_rn(acc[j][2] * dv2, acc[j][3] * dv2);
            *(__half2*)&g_bufA[(size_t)g2 * 64 + j * 8 + cq] = h;
        }
    }
}

__global__ void __launch_bounds__(256) k_gemm1(const float* __restrict__ x,
                                               const float* __restrict__ W) {
    gemm_core(x, W);
}
__global__ void __launch_bounds__(256) k_gemm23(const float* __restrict__ W) {
    gemm_core(0, W);
}

// ---------------- binned aggregation (warp per destination) -> activated fp16 bufC ----------
// bufC[c] = relu( dinv[c]*(edge_sum + self) + bias ) * bnsc[l] + bnsh[l]
__global__ void __launch_bounds__(256) k_agg(const float* __restrict__ bias, int l) {
    int warp = threadIdx.x >> 5;
    int lane = threadIdx.x & 31;
    int c = blockIdx.x * 8 + warp;          // NN % 8 == 0
    int half = lane >> 4;
    int q = lane & 15;
    int cnt = g_cursor[c];
    if (cnt > SLOT) cnt = SLOT;
    const int2* __restrict__ pay = g_pay + (size_t)c * SLOT;

    const uint2* __restrict__ A2 = (const uint2*)g_bufA;   // 16 uint2 per 64-feat row

    float4 acc = make_float4(0.f, 0.f, 0.f, 0.f);
    for (int e = half; e < cnt; e += 2) {
        int2 p = __ldg(&pay[e]);
        uint2 r = __ldg(&A2[(size_t)p.x * 16 + q]);
        float n = __int_as_float(p.y);
        float2 f0 = __half22float2(*(__half2*)&r.x);
        float2 f1 = __half22float2(*(__half2*)&r.y);
        acc.x += f0.x * n; acc.y += f0.y * n;
        acc.z += f1.x * n; acc.w += f1.y * n;
    }
    acc.x += __shfl_xor_sync(0xFFFFFFFFu, acc.x, 16);
    acc.y += __shfl_xor_sync(0xFFFFFFFFu, acc.y, 16);
    acc.z += __shfl_xor_sync(0xFFFFFFFFu, acc.z, 16);
    acc.w += __shfl_xor_sync(0xFFFFFFFFu, acc.w, 16);

    if (half == 0) {
        float dv = g_dinv[c];
        uint2 sr = __ldg(&A2[(size_t)c * 16 + q]);         // bufA'[c] = h[c]*dinv[c]
        float2 s0 = __half22float2(*(__half2*)&sr.x);
        float2 s1 = __half22float2(*(__half2*)&sr.y);
        float4 b = *(const float4*)(bias + q * 4);
        float4 sc = *(const float4*)&g_bnsc[l][q * 4];
        float4 sh = *(const float4*)&g_bnsh[l][q * 4];
        float o0 = fmaxf((acc.x + s0.x) * dv + b.x, 0.f) * sc.x + sh.x;
        float o1 = fmaxf((acc.y + s0.y) * dv + b.y, 0.f) * sc.y + sh.y;
        float o2 = fmaxf((acc.z + s1.x) * dv + b.z, 0.f) * sc.z + sh.z;
        float o3 = fmaxf((acc.w + s1.y) * dv + b.w, 0.f) * sc.w + sh.w;
        __half2 h0 = __floats2half2_rn(o0, o1);
        __half2 h1 = __floats2half2_rn(o2, o3);
        *(uint2*)&g_bufC[(size_t)c * 64 + q * 4] =
            make_uint2(*(unsigned*)&h0, *(unsigned*)&h1);
    }
}

// ---------------- layer-3 aggregation + BN3 + global_add_pool ----------------
__global__ void __launch_bounds__(256) k_agg3(const float* __restrict__ bias,
                                              const int* __restrict__ batch) {
    __shared__ float sacc[64];
    __shared__ int sbatch[8];
    int warp = threadIdx.x >> 5;
    int lane = threadIdx.x & 31;
    int c = blockIdx.x * 8 + warp;          // NN % 8 == 0
    int half = lane >> 4;
    int q = lane & 15;
    int cnt = g_cursor[c];
    if (cnt > SLOT) cnt = SLOT;
    const int2* __restrict__ pay = g_pay + (size_t)c * SLOT;
    const uint2* __restrict__ A2 = (const uint2*)g_bufA;

    if (threadIdx.x < 64) sacc[threadIdx.x] = 0.f;
    if (lane == 0) sbatch[warp] = batch[c];

    float4 acc = make_float4(0.f, 0.f, 0.f, 0.f);
    for (int e = half; e < cnt; e += 2) {
        int2 p = __ldg(&pay[e]);
        uint2 r = __ldg(&A2[(size_t)p.x * 16 + q]);
        float n = __int_as_float(p.y);
        float2 f0 = __half22float2(*(__half2*)&r.x);
        float2 f1 = __half22float2(*(__half2*)&r.y);
        acc.x += f0.x * n; acc.y += f0.y * n;
        acc.z += f1.x * n; acc.w += f1.y * n;
    }
    acc.x += __shfl_xor_sync(0xFFFFFFFFu, acc.x, 16);
    acc.y += __shfl_xor_sync(0xFFFFFFFFu, acc.y, 16);
    acc.z += __shfl_xor_sync(0xFFFFFFFFu, acc.z, 16);
    acc.w += __shfl_xor_sync(0xFFFFFFFFu, acc.w, 16);

    __syncthreads();
    bool uni = true;
#pragma unroll
    for (int i = 1; i < 8; i++) uni &= (sbatch[i] == sbatch[0]);

    if (half == 0) {
        float dv = g_dinv[c];
        uint2 sr = __ldg(&A2[(size_t)c * 16 + q]);
        float2 s0 = __half22float2(*(__half2*)&sr.x);
        float2 s1 = __half22float2(*(__half2*)&sr.y);
        float4 b = *(const float4*)(bias + q * 4);
        float4 sc = *(const float4*)&g_bnsc[2][q * 4];
        float4 sh = *(const float4*)&g_bnsh[2][q * 4];
        float o0 = ((acc.x + s0.x) * dv + b.x) * sc.x + sh.x;
        float o1 = ((acc.y + s0.y) * dv + b.y) * sc.y + sh.y;
        float o2 = ((acc.z + s1.x) * dv + b.z) * sc.z + sh.z;
        float o3 = ((acc.w + s1.y) * dv + b.w) * sc.w + sh.w;
        if (uni) {
            atomicAdd(&sacc[q * 4 + 0], o0);
            atomicAdd(&sacc[q * 4 + 1], o1);
            atomicAdd(&sacc[q * 4 + 2], o2);
            atomicAdd(&sacc[q * 4 + 3], o3);
        } else {
            int bg = sbatch[warp];
            atomicAdd(&g_pooled[bg * 64 + q * 4 + 0], o0);
            atomicAdd(&g_pooled[bg * 64 + q * 4 + 1], o1);
            atomicAdd(&g_pooled[bg * 64 + q * 4 + 2], o2);
            atomicAdd(&g_pooled[bg * 64 + q * 4 + 3], o3);
        }
    }
    __syncthreads();
    if (uni && threadIdx.x < 64)
        atomicAdd(&g_pooled[sbatch[0] * 64 + threadIdx.x], sacc[threadIdx.x]);
}

// ---------------- FC: out[g] = relu(pooled[g]) . Wfc + bfc ----------------
__global__ void k_fc(const float* __restrict__ Wfc, const float* __restrict__ bfc,
                     float* __restrict__ out) {
    int g = threadIdx.x;  // 128
    float acc = 0.f;
#pragma unroll
    for (int k = 0; k < 64; k++)
        acc += fmaxf(g_pooled[g * 64 + k], 0.f) * Wfc[k];
    out[g] = acc + bfc[0];
}

// ---------------- launch ----------------
extern "C" void kernel_launch(void* const* d_in, const int* in_sizes, int n_in,
                              void* d_out, int out_size) {
    const float* x     = (const float*)d_in[0];
    const int*   ei    = (const int*)d_in[1];
    const int*   row   = ei;
    const int*   col   = ei + EE;
    const float* ew    = (const float*)d_in[2];
    const int*   batch = (const int*)d_in[3];
    const float* W1 = (const float*)d_in[4];
    const float* b1 = (const float*)d_in[5];
    const float* W2 = (const float*)d_in[6];
    const float* b2 = (const float*)d_in[7];
    const float* W3 = (const float*)d_in[8];
    const float* b3 = (const float*)d_in[9];
    const float* Wfc = (const float*)d_in[10];
    const float* bfc = (const float*)d_in[11];

    BNParams bp;
    for (int i = 0; i < 12; i++) bp.p[i] = (const float*)d_in[12 + i];

    int nb_n = (NN + 255) / 256;            // 391
    int nb_e = (EE + 255) / 256;            // 6250
    int nb_gemm = (NN + 127) / 128;         // 782 (one 128-row tile per 256-thread block)
    int nb_agg = NN / 8;                    // 12500

    // build: bin edges, then derive dinv from bins
    k_prep<<<nb_n, 256>>>(bp);
    k_scatter<<<nb_e, 256>>>(row, col, ew);
    k_fin<<<nb_n, 256>>>();

    // layer 1 (fp32 input)
    k_gemm1<<<nb_gemm, 256>>>(x, W1);
    k_agg<<<nb_agg, 256>>>(b1, 0);
    // layer 2 (activated fp16 input)
    k_gemm23<<<nb_gemm, 256>>>(W2);
    k_agg<<<nb_agg, 256>>>(b2, 1);
    // layer 3 + fused BN3/pool
    k_gemm23<<<nb_gemm, 256>>>(W3);
    k_agg3<<<nb_agg, 256>>>(b3, batch);

    // fc
    k_fc<<<1, 128>>>(Wfc, bfc, (float*)d_out);
}